// round 1
// baseline (speedup 1.0000x reference)
#include <cuda_runtime.h>
#include <math.h>

#define NPTS   32768
#define NEDGE  524288
#define NBATCH 2
#define HID    64
#define LIFTD  256
#define NLAYER 4

// ---------------- scratch (no allocations allowed) ----------------
__device__ float d_h[NBATCH * NPTS * HID];     // 16 MB
__device__ float d_A[NBATCH * NPTS * HID];     // 16 MB   A[b,n] = h@W[4:68] + pos@W[0:2]
__device__ float d_Pd[NPTS * HID];             // 8 MB    Pd[n] = pos@W[2:4] + kb1
__device__ float d_agg[NBATCH * NPTS * HID];   // 16 MB
__device__ float d_invc[NPTS];
__device__ int   d_deg[NPTS];
__device__ int   d_is64;

__device__ __forceinline__ float gelu_f(float v) {
    return 0.5f * v * (1.0f + erff(v * 0.70710678118654752f));
}

// ---------------- edge index dtype detection ----------------
// jnp.int64 requested, but JAX default config demotes to int32. Detect on device:
// if data is int32, an int64 view combines random index pairs -> values >= NPTS
// with prob ~1 per sample.
__global__ void k_detect(const void* __restrict__ ei) {
    __shared__ int bad;
    if (threadIdx.x == 0) bad = 0;
    __syncthreads();
    long long v = ((const long long*)ei)[threadIdx.x];
    if (v < 0 || v >= NPTS) atomicOr(&bad, 1);
    __syncthreads();
    if (threadIdx.x == 0) d_is64 = bad ? 0 : 1;
}

// ---------------- degree ----------------
__global__ void k_zero_deg() {
    int i = blockIdx.x * blockDim.x + threadIdx.x;
    if (i < NPTS) d_deg[i] = 0;
}

__global__ void k_count(const void* __restrict__ ei) {
    int e = blockIdx.x * blockDim.x + threadIdx.x;
    if (e < NEDGE) {
        int dd = d_is64 ? (int)((const long long*)ei)[NEDGE + e]
                        : ((const int*)ei)[NEDGE + e];
        atomicAdd(&d_deg[dd], 1);
    }
}

__global__ void k_inv() {
    int i = blockIdx.x * blockDim.x + threadIdx.x;
    if (i < NPTS) d_invc[i] = 1.0f / fmaxf((float)d_deg[i], 1.0f);
}

// ---------------- lift: h = gelu([x,pos]@w1+b1)@w2+b2 ----------------
// 16 node-batch items per block, 256 threads.
__global__ void __launch_bounds__(256) k_lift(
    const float* __restrict__ x, const float* __restrict__ pos,
    const float* __restrict__ w1, const float* __restrict__ b1,
    const float* __restrict__ w2, const float* __restrict__ b2)
{
    __shared__ float in_s[16][5];
    __shared__ float t_s[16][LIFTD];
    int t = threadIdx.x;
    int item0 = blockIdx.x * 16;

    if (t < 80) {
        int j = t / 5, i = t % 5;
        int item = item0 + j;
        int b = item >> 15, n = item & (NPTS - 1);
        in_s[j][i] = (i < 3) ? x[((size_t)b * NPTS + n) * 3 + i] : pos[n * 2 + (i - 3)];
    }
    __syncthreads();
    {
        int c = t;
        float w0 = w1[c], wA = w1[LIFTD + c], wB = w1[2 * LIFTD + c];
        float wC = w1[3 * LIFTD + c], wD = w1[4 * LIFTD + c];
        float bc = b1[c];
#pragma unroll
        for (int j = 0; j < 16; j++) {
            float v = bc + in_s[j][0] * w0 + in_s[j][1] * wA + in_s[j][2] * wB
                         + in_s[j][3] * wC + in_s[j][4] * wD;
            t_s[j][c] = gelu_f(v);
        }
    }
    __syncthreads();
    {
        int c = t & 63, jg = t >> 6;    // 4 groups x 4 nodes
        int jb = jg * 4;
        float a0 = b2[c], a1 = a0, a2 = a0, a3 = a0;
#pragma unroll 4
        for (int k = 0; k < LIFTD; k++) {
            float w = w2[k * HID + c];
            a0 += t_s[jb + 0][k] * w;
            a1 += t_s[jb + 1][k] * w;
            a2 += t_s[jb + 2][k] * w;
            a3 += t_s[jb + 3][k] * w;
        }
        d_h[(item0 + jb + 0) * HID + c] = a0;
        d_h[(item0 + jb + 1) * HID + c] = a1;
        d_h[(item0 + jb + 2) * HID + c] = a2;
        d_h[(item0 + jb + 3) * HID + c] = a3;
    }
}

// ---------------- Pd[n,c] = kb1[c] + pos[n,0]*W1[2,c] + pos[n,1]*W1[3,c] ----
__global__ void __launch_bounds__(256) k_Pd(
    const float* __restrict__ pos, const float* __restrict__ kW1_l,
    const float* __restrict__ kb1_l)
{
    int i = blockIdx.x * blockDim.x + threadIdx.x;   // NPTS*64
    int n = i >> 6, c = i & 63;
    d_Pd[i] = kb1_l[c] + pos[n * 2] * kW1_l[2 * 64 + c] + pos[n * 2 + 1] * kW1_l[3 * 64 + c];
}

// ---------------- A[b,n] = h[b,n]@W1[4:68] + pos@W1[0:2] -------------------
// 8 items per block, 256 threads; W staged in smem.
__global__ void __launch_bounds__(256) k_A(
    const float* __restrict__ pos, const float* __restrict__ kW1_l)
{
    __shared__ float W_s[64 * 64];
    __shared__ float pw0[64], pw1[64];
    __shared__ float h_s[8 * 64];
    __shared__ float pos_s[8][2];
    int t = threadIdx.x;
    int item0 = blockIdx.x * 8;

#pragma unroll
    for (int r = 0; r < 16; r++) W_s[t + 256 * r] = kW1_l[4 * 64 + t + 256 * r];
    if (t < 64) { pw0[t] = kW1_l[t]; pw1[t] = kW1_l[64 + t]; }
#pragma unroll
    for (int r = 0; r < 2; r++) h_s[t + 256 * r] = d_h[item0 * 64 + t + 256 * r];
    if (t < 16) {
        int j = t >> 1, i = t & 1;
        int item = item0 + j;
        int n = item & (NPTS - 1);
        pos_s[j][i] = pos[n * 2 + i];
    }
    __syncthreads();

    int c = t & 63, jg = t >> 6;
    int j0 = jg * 2, j1 = j0 + 1;
    float a0 = pos_s[j0][0] * pw0[c] + pos_s[j0][1] * pw1[c];
    float a1 = pos_s[j1][0] * pw0[c] + pos_s[j1][1] * pw1[c];
#pragma unroll 4
    for (int k = 0; k < 64; k++) {
        float w = W_s[k * 64 + c];
        a0 += h_s[j0 * 64 + k] * w;
        a1 += h_s[j1 * 64 + k] * w;
    }
    d_A[item0 * 64 + j0 * 64 + c] = a0;
    d_A[item0 * 64 + j1 * 64 + c] = a1;
}

// ---------------- zero agg ----------------
__global__ void __launch_bounds__(256) k_zero_agg() {
    int i = blockIdx.x * blockDim.x + threadIdx.x;   // NBATCH*NPTS*HID/4
    float4 z = make_float4(0.f, 0.f, 0.f, 0.f);
    ((float4*)d_agg)[i] = z;
}

// ---------------- edge kernel: m = gelu(A[src]+Pd[dst]) @ kW2 + kb2 ; scatter
// 64 edges per block, 256 threads. kW2 in smem (float4 rows), g in smem (pad 68).
__global__ void __launch_bounds__(256) k_edge(
    const void* __restrict__ ei, const float* __restrict__ kW2_l,
    const float* __restrict__ kb2_l)
{
    __shared__ __align__(16) float W_s[64 * 64];   // 16 KB
    __shared__ float g_s[64 * 68];                 // 17.4 KB
    __shared__ float kb2_s[64];
    __shared__ int src_s[64], dst_s[64];

    int t = threadIdx.x;
    int e_base = blockIdx.x * 64;
    int is64 = d_is64;

#pragma unroll
    for (int r = 0; r < 16; r++) W_s[t + 256 * r] = kW2_l[t + 256 * r];
    if (t < 64) {
        kb2_s[t] = kb2_l[t];
        if (is64) {
            src_s[t] = (int)((const long long*)ei)[e_base + t];
            dst_s[t] = (int)((const long long*)ei)[NEDGE + e_base + t];
        } else {
            src_s[t] = ((const int*)ei)[e_base + t];
            dst_s[t] = ((const int*)ei)[NEDGE + e_base + t];
        }
    }
    __syncthreads();

    int c  = t & 63, e4 = t >> 6;    // phase1 mapping
    int ci = t & 7,  eg = t >> 3;    // phase2 mapping: 8 cols x (2 edges: eg, eg+32)
    const float4* W4 = (const float4*)W_s;

    for (int b = 0; b < NBATCH; b++) {
        // phase 1: g = gelu(A[b,src] + Pd[dst]) for 64 edges x 64 channels
#pragma unroll
        for (int r = 0; r < 16; r++) {
            int e = e4 + 4 * r;
            int s = src_s[e], dd = dst_s[e];
            float v = d_A[(b * NPTS + s) * 64 + c] + d_Pd[dd * 64 + c];
            g_s[e * 68 + c] = gelu_f(v);
        }
        __syncthreads();

        // phase 2: per-thread 2 edges x 8 output cols
        float acc0[8], acc1[8];
#pragma unroll
        for (int j = 0; j < 8; j++) { acc0[j] = kb2_s[ci * 8 + j]; acc1[j] = acc0[j]; }

#pragma unroll 4
        for (int k = 0; k < 64; k++) {
            float4 wA = W4[k * 16 + ci * 2];
            float4 wB = W4[k * 16 + ci * 2 + 1];
            float g0 = g_s[eg * 68 + k];
            float g1 = g_s[(eg + 32) * 68 + k];
            acc0[0] += g0 * wA.x; acc0[1] += g0 * wA.y; acc0[2] += g0 * wA.z; acc0[3] += g0 * wA.w;
            acc0[4] += g0 * wB.x; acc0[5] += g0 * wB.y; acc0[6] += g0 * wB.z; acc0[7] += g0 * wB.w;
            acc1[0] += g1 * wA.x; acc1[1] += g1 * wA.y; acc1[2] += g1 * wA.z; acc1[3] += g1 * wA.w;
            acc1[4] += g1 * wB.x; acc1[5] += g1 * wB.y; acc1[6] += g1 * wB.z; acc1[7] += g1 * wB.w;
        }

        float* base0 = d_agg + ((size_t)(b * NPTS + dst_s[eg])) * 64 + ci * 8;
        float* base1 = d_agg + ((size_t)(b * NPTS + dst_s[eg + 32])) * 64 + ci * 8;
        asm volatile("red.global.add.v4.f32 [%0], {%1,%2,%3,%4};" ::
                     "l"(base0), "f"(acc0[0]), "f"(acc0[1]), "f"(acc0[2]), "f"(acc0[3]) : "memory");
        asm volatile("red.global.add.v4.f32 [%0], {%1,%2,%3,%4};" ::
                     "l"(base0 + 4), "f"(acc0[4]), "f"(acc0[5]), "f"(acc0[6]), "f"(acc0[7]) : "memory");
        asm volatile("red.global.add.v4.f32 [%0], {%1,%2,%3,%4};" ::
                     "l"(base1), "f"(acc1[0]), "f"(acc1[1]), "f"(acc1[2]), "f"(acc1[3]) : "memory");
        asm volatile("red.global.add.v4.f32 [%0], {%1,%2,%3,%4};" ::
                     "l"(base1 + 4), "f"(acc1[4]), "f"(acc1[5]), "f"(acc1[6]), "f"(acc1[7]) : "memory");
        __syncthreads();   // g_s reuse for next batch
    }
}

// ---------------- h += agg * inv_cnt ----------------
__global__ void __launch_bounds__(256) k_update() {
    int i = blockIdx.x * blockDim.x + threadIdx.x;   // NBATCH*NPTS*HID/4
    int item = i >> 4;
    int n = item & (NPTS - 1);
    float ic = d_invc[n];
    float4 h = ((float4*)d_h)[i];
    float4 a = ((float4*)d_agg)[i];
    h.x += a.x * ic; h.y += a.y * ic; h.z += a.z * ic; h.w += a.w * ic;
    ((float4*)d_h)[i] = h;
}

// ---------------- proj: out = gelu(h@w1+b1)@w2+b2 ----------------
// 8 items per block, 256 threads; one warp per item for the final reduction.
__global__ void __launch_bounds__(256) k_proj(
    const float* __restrict__ w1, const float* __restrict__ b1,
    const float* __restrict__ w2, const float* __restrict__ b2,
    float* __restrict__ out)
{
    __shared__ float h_s[8 * 64];
    __shared__ float t_s[8][256];
    __shared__ float w2_s[256];
    int t = threadIdx.x;
    int item0 = blockIdx.x * 8;

#pragma unroll
    for (int r = 0; r < 2; r++) h_s[t + 256 * r] = d_h[item0 * 64 + t + 256 * r];
    w2_s[t] = w2[t];
    __syncthreads();
    {
        int c = t;
        float acc[8];
        float bc = b1[c];
#pragma unroll
        for (int j = 0; j < 8; j++) acc[j] = bc;
#pragma unroll 4
        for (int k = 0; k < 64; k++) {
            float w = w1[k * 256 + c];
#pragma unroll
            for (int j = 0; j < 8; j++) acc[j] += h_s[j * 64 + k] * w;
        }
#pragma unroll
        for (int j = 0; j < 8; j++) t_s[j][c] = gelu_f(acc[j]);
    }
    __syncthreads();
    {
        int w = t >> 5, lane = t & 31;
        float p = 0.f;
#pragma unroll
        for (int r = 0; r < 8; r++) {
            int cc = lane + 32 * r;
            p += t_s[w][cc] * w2_s[cc];
        }
#pragma unroll
        for (int o = 16; o > 0; o >>= 1) p += __shfl_down_sync(0xffffffffu, p, o);
        if (lane == 0) out[item0 + w] = p + b2[0];   // out[b,0,n] flat = b*NPTS+n
    }
}

// ---------------- launch ----------------
extern "C" void kernel_launch(void* const* d_in, const int* in_sizes, int n_in,
                              void* d_out, int out_size) {
    (void)in_sizes; (void)n_in; (void)out_size;
    const float* x    = (const float*)d_in[0];
    const float* pos  = (const float*)d_in[1];
    const void*  ei   = d_in[2];
    const float* lw1  = (const float*)d_in[3];
    const float* lb1  = (const float*)d_in[4];
    const float* lw2  = (const float*)d_in[5];
    const float* lb2  = (const float*)d_in[6];
    const float* kW1  = (const float*)d_in[7];
    const float* kb1  = (const float*)d_in[8];
    const float* kW2  = (const float*)d_in[9];
    const float* kb2  = (const float*)d_in[10];
    const float* pw1  = (const float*)d_in[11];
    const float* pb1  = (const float*)d_in[12];
    const float* pw2  = (const float*)d_in[13];
    const float* pb2  = (const float*)d_in[14];
    float* out = (float*)d_out;

    k_detect<<<1, 128>>>(ei);
    k_lift<<<(NBATCH * NPTS) / 16, 256>>>(x, pos, lw1, lb1, lw2, lb2);

    k_zero_deg<<<(NPTS + 255) / 256, 256>>>();
    k_count<<<(NEDGE + 255) / 256, 256>>>(ei);
    k_inv<<<(NPTS + 255) / 256, 256>>>();

    for (int l = 0; l < NLAYER; l++) {
        const float* W1l = kW1 + (size_t)l * 68 * 64;
        const float* b1l = kb1 + (size_t)l * 64;
        const float* W2l = kW2 + (size_t)l * 64 * 64;
        const float* b2l = kb2 + (size_t)l * 64;
        k_Pd<<<(NPTS * 64) / 256, 256>>>(pos, W1l, b1l);
        k_A<<<(NBATCH * NPTS) / 8, 256>>>(pos, W1l);
        k_zero_agg<<<(NBATCH * NPTS * HID / 4) / 256, 256>>>();
        k_edge<<<NEDGE / 64, 256>>>(ei, W2l, b2l);
        k_update<<<(NBATCH * NPTS * HID / 4) / 256, 256>>>();
    }

    k_proj<<<(NBATCH * NPTS) / 8, 256>>>(pw1, pb1, pw2, pb2, out);
}

// round 3
// speedup vs baseline: 1.9243x; 1.9243x over previous
#include <cuda_runtime.h>
#include <math.h>
#include <stdint.h>

#define NPTS   32768
#define NEDGE  524288
#define NBATCH 2
#define HID    64
#define LIFTD  256
#define NLAYER 4

// ---------------- scratch ----------------
__device__ float d_h[NBATCH * NPTS * HID];
__device__ float d_A[NBATCH * NPTS * HID];
__device__ float d_Pd[NPTS * HID];
__device__ float d_agg[NBATCH * NPTS * HID];
__device__ float d_invc[NPTS];
__device__ int   d_deg[NPTS];
__device__ int   d_is64;

__device__ __forceinline__ float gelu_f(float v) {
    return 0.5f * v * (1.0f + erff(v * 0.70710678118654752f));
}

__device__ __forceinline__ uint32_t f2tf32(float f) {
    uint32_t r;
    asm("cvt.rna.tf32.f32 %0, %1;" : "=r"(r) : "f"(f));
    return r;
}

__device__ __forceinline__ void mma_tf32(float* d, const uint32_t* a, const uint32_t* b) {
    asm volatile("mma.sync.aligned.m16n8k8.row.col.f32.tf32.tf32.f32 "
                 "{%0,%1,%2,%3}, {%4,%5,%6,%7}, {%8,%9}, {%0,%1,%2,%3};"
                 : "+f"(d[0]), "+f"(d[1]), "+f"(d[2]), "+f"(d[3])
                 : "r"(a[0]), "r"(a[1]), "r"(a[2]), "r"(a[3]), "r"(b[0]), "r"(b[1]));
}

// ---------------- k_init: zero agg + deg, detect edge dtype ----------------
__global__ void __launch_bounds__(256) k_init(const void* __restrict__ ei) {
    int t = threadIdx.x;
    int i = blockIdx.x * 256 + t;
    ((float4*)d_agg)[i] = make_float4(0.f, 0.f, 0.f, 0.f);
    if (i < NPTS) d_deg[i] = 0;
    if (blockIdx.x == 4095) {
        __shared__ int bad;
        if (t == 0) bad = 0;
        __syncthreads();
        if (t < 128) {
            long long v = ((const long long*)ei)[t];
            if (v < 0 || v >= NPTS) atomicOr(&bad, 1);
        }
        __syncthreads();
        if (t == 0) d_is64 = bad ? 0 : 1;
    }
}

__global__ void k_count(const void* __restrict__ ei) {
    int e = blockIdx.x * blockDim.x + threadIdx.x;
    if (e < NEDGE) {
        int dd = d_is64 ? (int)((const long long*)ei)[NEDGE + e]
                        : ((const int*)ei)[NEDGE + e];
        atomicAdd(&d_deg[dd], 1);
    }
}

__global__ void k_inv() {
    int i = blockIdx.x * blockDim.x + threadIdx.x;
    if (i < NPTS) d_invc[i] = 1.0f / fmaxf((float)d_deg[i], 1.0f);
}

// ---------------- lift ----------------
__global__ void __launch_bounds__(256) k_lift(
    const float* __restrict__ x, const float* __restrict__ pos,
    const float* __restrict__ w1, const float* __restrict__ b1,
    const float* __restrict__ w2, const float* __restrict__ b2)
{
    __shared__ float in_s[16][5];
    __shared__ float t_s[16][LIFTD];
    int t = threadIdx.x;
    int item0 = blockIdx.x * 16;

    if (t < 80) {
        int j = t / 5, i = t % 5;
        int item = item0 + j;
        int b = item >> 15, n = item & (NPTS - 1);
        in_s[j][i] = (i < 3) ? x[((size_t)b * NPTS + n) * 3 + i] : pos[n * 2 + (i - 3)];
    }
    __syncthreads();
    {
        int c = t;
        float w0 = w1[c], wA = w1[LIFTD + c], wB = w1[2 * LIFTD + c];
        float wC = w1[3 * LIFTD + c], wD = w1[4 * LIFTD + c];
        float bc = b1[c];
#pragma unroll
        for (int j = 0; j < 16; j++) {
            float v = bc + in_s[j][0] * w0 + in_s[j][1] * wA + in_s[j][2] * wB
                         + in_s[j][3] * wC + in_s[j][4] * wD;
            t_s[j][c] = gelu_f(v);
        }
    }
    __syncthreads();
    {
        int c = t & 63, jg = t >> 6;
        int jb = jg * 4;
        float a0 = b2[c], a1 = a0, a2 = a0, a3 = a0;
#pragma unroll 4
        for (int k = 0; k < LIFTD; k++) {
            float w = w2[k * HID + c];
            a0 += t_s[jb + 0][k] * w;
            a1 += t_s[jb + 1][k] * w;
            a2 += t_s[jb + 2][k] * w;
            a3 += t_s[jb + 3][k] * w;
        }
        d_h[(item0 + jb + 0) * HID + c] = a0;
        d_h[(item0 + jb + 1) * HID + c] = a1;
        d_h[(item0 + jb + 2) * HID + c] = a2;
        d_h[(item0 + jb + 3) * HID + c] = a3;
    }
}

// ---------------- A (and Pd) ----------------
__global__ void __launch_bounds__(256) k_APd(
    const float* __restrict__ pos, const float* __restrict__ kW1_l,
    const float* __restrict__ kb1_l)
{
    __shared__ float W_s[64 * 64];
    __shared__ float pw0[64], pw1[64];
    __shared__ float h_s[8 * 64];
    __shared__ float pos_s[8][2];
    int t = threadIdx.x;
    int item0 = blockIdx.x * 8;

    if (item0 < NPTS) {
#pragma unroll
        for (int r = 0; r < 2; r++) {
            int i = t + 256 * r;
            int n = item0 + (i >> 6), c = i & 63;
            d_Pd[n * 64 + c] = kb1_l[c] + pos[n * 2] * kW1_l[2 * 64 + c]
                                        + pos[n * 2 + 1] * kW1_l[3 * 64 + c];
        }
    }

#pragma unroll
    for (int r = 0; r < 16; r++) W_s[t + 256 * r] = kW1_l[4 * 64 + t + 256 * r];
    if (t < 64) { pw0[t] = kW1_l[t]; pw1[t] = kW1_l[64 + t]; }
#pragma unroll
    for (int r = 0; r < 2; r++) h_s[t + 256 * r] = d_h[item0 * 64 + t + 256 * r];
    if (t < 16) {
        int j = t >> 1, i = t & 1;
        int n = (item0 + j) & (NPTS - 1);
        pos_s[j][i] = pos[n * 2 + i];
    }
    __syncthreads();

    int c = t & 63, jg = t >> 6;
    int j0 = jg * 2, j1 = j0 + 1;
    float a0 = pos_s[j0][0] * pw0[c] + pos_s[j0][1] * pw1[c];
    float a1 = pos_s[j1][0] * pw0[c] + pos_s[j1][1] * pw1[c];
#pragma unroll 4
    for (int k = 0; k < 64; k++) {
        float w = W_s[k * 64 + c];
        a0 += h_s[j0 * 64 + k] * w;
        a1 += h_s[j1 * 64 + k] * w;
    }
    d_A[item0 * 64 + j0 * 64 + c] = a0;
    d_A[item0 * 64 + j1 * 64 + c] = a1;
}

// ---------------- edge kernel: mma.sync tf32, 128 edges/block ----------------
// smem layout (dynamic):
//   g_s : 128 x 68 u32/float (A tile, tf32; reused to stage C)   34816 B
//   w_s : 64  x 72 u32 (B tile = kW2 in native [k][n], tf32)     18432 B
//   bias_s : 64 f                                                  256 B
//   src_s, dst_s : 128 int each                                   1024 B
#define G_STRIDE 68
#define W_STRIDE 72
#define G_BYTES  (128 * G_STRIDE * 4)
#define W_BYTES  (64 * W_STRIDE * 4)
#define EDGE_SMEM (G_BYTES + W_BYTES + 256 + 1024)

__global__ void __launch_bounds__(256) k_edge(
    const void* __restrict__ ei, const float* __restrict__ kW2_l,
    const float* __restrict__ kb2_l)
{
    extern __shared__ char smem[];
    uint32_t* g_s  = (uint32_t*)smem;
    float*    g_sf = (float*)smem;
    uint32_t* w_s  = (uint32_t*)(smem + G_BYTES);
    float*    bias_s = (float*)(smem + G_BYTES + W_BYTES);
    int*      src_s  = (int*)(smem + G_BYTES + W_BYTES + 256);
    int*      dst_s  = (int*)(smem + G_BYTES + W_BYTES + 768);

    int t = threadIdx.x;
    int e_base = blockIdx.x * 128;
    int is64 = d_is64;

    // stage W2 (native [k][n]) as tf32
#pragma unroll
    for (int r = 0; r < 16; r++) {
        int i = t + 256 * r;
        int k = i >> 6, n = i & 63;
        w_s[k * W_STRIDE + n] = f2tf32(kW2_l[i]);
    }
    if (t < 128) {
        if (is64) {
            src_s[t] = (int)((const long long*)ei)[e_base + t];
            dst_s[t] = (int)((const long long*)ei)[NEDGE + e_base + t];
        } else {
            src_s[t] = ((const int*)ei)[e_base + t];
            dst_s[t] = ((const int*)ei)[NEDGE + e_base + t];
        }
    }
    if (t < 64) bias_s[t] = kb2_l[t];
    __syncthreads();

    int c  = t & 63, eg = t >> 6;            // phase1 mapping
    int w  = t >> 5, lane = t & 31;          // phase2 mapping
    int r  = lane >> 2, c4 = lane & 3;
    int m0 = w * 16;
    int se = t & 127, half = t >> 7;         // scatter mapping

    for (int b = 0; b < NBATCH; b++) {
        const float* Ab = d_A + (size_t)b * NPTS * 64;

        // phase 1: g = tf32(gelu(A[src] + Pd[dst]))
#pragma unroll 4
        for (int rr = 0; rr < 32; rr++) {
            int e = eg * 32 + rr;
            float v = Ab[(size_t)src_s[e] * 64 + c] + d_Pd[(size_t)dst_s[e] * 64 + c];
            g_s[e * G_STRIDE + c] = f2tf32(gelu_f(v));
        }
        __syncthreads();

        // phase 2: warp w computes edges [m0, m0+16) x 64 cols
        float acc[8][4];
#pragma unroll
        for (int j = 0; j < 8; j++) {
            float b0 = bias_s[j * 8 + c4 * 2];
            float b1 = bias_s[j * 8 + c4 * 2 + 1];
            acc[j][0] = b0; acc[j][1] = b1; acc[j][2] = b0; acc[j][3] = b1;
        }
#pragma unroll
        for (int kk = 0; kk < 8; kk++) {
            uint32_t a[4];
            a[0] = g_s[(m0 + r)     * G_STRIDE + kk * 8 + c4];
            a[1] = g_s[(m0 + r + 8) * G_STRIDE + kk * 8 + c4];
            a[2] = g_s[(m0 + r)     * G_STRIDE + kk * 8 + c4 + 4];
            a[3] = g_s[(m0 + r + 8) * G_STRIDE + kk * 8 + c4 + 4];
#pragma unroll
            for (int j = 0; j < 8; j++) {
                uint32_t bb[2];
                bb[0] = w_s[(kk * 8 + c4)     * W_STRIDE + j * 8 + r];
                bb[1] = w_s[(kk * 8 + c4 + 4) * W_STRIDE + j * 8 + r];
                mma_tf32(acc[j], a, bb);
            }
        }

        // stage C into g_s (warp-private rows; no sync needed before stores)
#pragma unroll
        for (int j = 0; j < 8; j++) {
            *(float2*)(g_sf + (m0 + r)     * G_STRIDE + j * 8 + c4 * 2) =
                make_float2(acc[j][0], acc[j][1]);
            *(float2*)(g_sf + (m0 + r + 8) * G_STRIDE + j * 8 + c4 * 2) =
                make_float2(acc[j][2], acc[j][3]);
        }
        __syncthreads();

        // scatter: thread -> edge se, cols [half*32, half*32+32)
        {
            float* base = d_agg + ((size_t)(b * NPTS + dst_s[se])) * 64 + half * 32;
            const float4* m4 = (const float4*)(g_sf + se * G_STRIDE + half * 32);
#pragma unroll
            for (int j = 0; j < 8; j++) {
                float4 v = m4[j];
                asm volatile("red.global.add.v4.f32 [%0], {%1,%2,%3,%4};" ::
                             "l"(base + 4 * j), "f"(v.x), "f"(v.y), "f"(v.z), "f"(v.w) : "memory");
            }
        }
        __syncthreads();   // g_s reuse for next batch
    }
}

// ---------------- update: h += agg * inv_cnt; re-zero agg ----------------
__global__ void __launch_bounds__(256) k_update() {
    int i = blockIdx.x * 256 + threadIdx.x;
    int item = i >> 4;
    int n = item & (NPTS - 1);
    float ic = d_invc[n];
    float4 h = ((float4*)d_h)[i];
    float4 a = ((float4*)d_agg)[i];
    h.x += a.x * ic; h.y += a.y * ic; h.z += a.z * ic; h.w += a.w * ic;
    ((float4*)d_h)[i] = h;
    ((float4*)d_agg)[i] = make_float4(0.f, 0.f, 0.f, 0.f);
}

// ---------------- proj ----------------
__global__ void __launch_bounds__(256) k_proj(
    const float* __restrict__ w1, const float* __restrict__ b1,
    const float* __restrict__ w2, const float* __restrict__ b2,
    float* __restrict__ out)
{
    __shared__ float h_s[8 * 64];
    __shared__ float t_s[8][256];
    __shared__ float w2_s[256];
    int t = threadIdx.x;
    int item0 = blockIdx.x * 8;

#pragma unroll
    for (int r = 0; r < 2; r++) h_s[t + 256 * r] = d_h[item0 * 64 + t + 256 * r];
    w2_s[t] = w2[t];
    __syncthreads();
    {
        int c = t;
        float acc[8];
        float bc = b1[c];
#pragma unroll
        for (int j = 0; j < 8; j++) acc[j] = bc;
#pragma unroll 4
        for (int k = 0; k < 64; k++) {
            float w = w1[k * 256 + c];
#pragma unroll
            for (int j = 0; j < 8; j++) acc[j] += h_s[j * 64 + k] * w;
        }
#pragma unroll
        for (int j = 0; j < 8; j++) t_s[j][c] = gelu_f(acc[j]);
    }
    __syncthreads();
    {
        int w = t >> 5, lane = t & 31;
        float p = 0.f;
#pragma unroll
        for (int r = 0; r < 8; r++) {
            int cc = lane + 32 * r;
            p += t_s[w][cc] * w2_s[cc];
        }
#pragma unroll
        for (int o = 16; o > 0; o >>= 1) p += __shfl_down_sync(0xffffffffu, p, o);
        if (lane == 0) out[item0 + w] = p + b2[0];
    }
}

// ---------------- launch ----------------
extern "C" void kernel_launch(void* const* d_in, const int* in_sizes, int n_in,
                              void* d_out, int out_size) {
    (void)in_sizes; (void)n_in; (void)out_size;
    const float* x    = (const float*)d_in[0];
    const float* pos  = (const float*)d_in[1];
    const void*  ei   = d_in[2];
    const float* lw1  = (const float*)d_in[3];
    const float* lb1  = (const float*)d_in[4];
    const float* lw2  = (const float*)d_in[5];
    const float* lb2  = (const float*)d_in[6];
    const float* kW1  = (const float*)d_in[7];
    const float* kb1  = (const float*)d_in[8];
    const float* kW2  = (const float*)d_in[9];
    const float* kb2  = (const float*)d_in[10];
    const float* pw1  = (const float*)d_in[11];
    const float* pb1  = (const float*)d_in[12];
    const float* pw2  = (const float*)d_in[13];
    const float* pb2  = (const float*)d_in[14];
    float* out = (float*)d_out;

    cudaFuncSetAttribute(k_edge, cudaFuncAttributeMaxDynamicSharedMemorySize, EDGE_SMEM);

    // launch order: index 5 (= ncu -s 5) is k_edge layer 0
    k_init<<<4096, 256>>>(ei);                                           // 0
    k_count<<<(NEDGE + 255) / 256, 256>>>(ei);                           // 1
    k_inv<<<(NPTS + 255) / 256, 256>>>();                                // 2
    k_lift<<<(NBATCH * NPTS) / 16, 256>>>(x, pos, lw1, lb1, lw2, lb2);   // 3

    for (int l = 0; l < NLAYER; l++) {
        const float* W1l = kW1 + (size_t)l * 68 * 64;
        const float* b1l = kb1 + (size_t)l * 64;
        const float* W2l = kW2 + (size_t)l * 64 * 64;
        const float* b2l = kb2 + (size_t)l * 64;
        k_APd<<<(NBATCH * NPTS) / 8, 256>>>(pos, W1l, b1l);              // 4,7,10,13
        k_edge<<<NEDGE / 128, 256, EDGE_SMEM>>>(ei, W2l, b2l);           // 5,8,11,14
        k_update<<<4096, 256>>>();                                       // 6,9,12,15
    }

    k_proj<<<(NBATCH * NPTS) / 8, 256>>>(pw1, pb1, pw2, pb2, out);       // 16
}

// round 4
// speedup vs baseline: 2.6352x; 1.3694x over previous
#include <cuda_runtime.h>
#include <math.h>
#include <stdint.h>

#define NPTS   32768
#define NEDGE  524288
#define NBATCH 2
#define HID    64
#define LIFTD  256
#define NLAYER 4

// ---------------- scratch ----------------
__device__ float d_h[NBATCH * NPTS * HID];
__device__ float d_A[NBATCH * NPTS * HID];
__device__ float d_Pd[NPTS * HID];
__device__ float d_agg[NBATCH * NPTS * HID];
__device__ float d_invc[NPTS];
__device__ int   d_deg[NPTS];
__device__ int   d_cursor[NPTS];
__device__ int   d_ssrc[NEDGE];
__device__ int   d_sdst[NEDGE];
__device__ int   d_is64;

__device__ __forceinline__ float gelu_f(float v) {
    return 0.5f * v * (1.0f + erff(v * 0.70710678118654752f));
}
__device__ __forceinline__ uint32_t f2tf32(float f) {
    uint32_t r;
    asm("cvt.rna.tf32.f32 %0, %1;" : "=r"(r) : "f"(f));
    return r;
}
__device__ __forceinline__ void mma_tf32(float* d, const uint32_t* a, const uint32_t* b) {
    asm volatile("mma.sync.aligned.m16n8k8.row.col.f32.tf32.tf32.f32 "
                 "{%0,%1,%2,%3}, {%4,%5,%6,%7}, {%8,%9}, {%0,%1,%2,%3};"
                 : "+f"(d[0]), "+f"(d[1]), "+f"(d[2]), "+f"(d[3])
                 : "r"(a[0]), "r"(a[1]), "r"(a[2]), "r"(a[3]), "r"(b[0]), "r"(b[1]));
}
__device__ __forceinline__ void red4(float* p, float4 v) {
    asm volatile("red.global.add.v4.f32 [%0], {%1,%2,%3,%4};" ::
                 "l"(p), "f"(v.x), "f"(v.y), "f"(v.z), "f"(v.w) : "memory");
}

#define G_STRIDE 68
#define W_STRIDE 72

// ---------------- k_detect: zero deg + dtype detect ----------------
__global__ void __launch_bounds__(256) k_detect(const void* __restrict__ ei) {
    int t = threadIdx.x;
#pragma unroll
    for (int r = 0; r < 32; r++)
        ((int4*)d_deg)[t + 256 * r] = make_int4(0, 0, 0, 0);
    __shared__ int bad;
    if (t == 0) bad = 0;
    __syncthreads();
    if (t < 128) {
        long long v = ((const long long*)ei)[t];
        if (v < 0 || v >= NPTS) atomicOr(&bad, 1);
    }
    __syncthreads();
    if (t == 0) d_is64 = bad ? 0 : 1;
}

// ---------------- k_count ----------------
__global__ void k_count(const void* __restrict__ ei) {
    int e = blockIdx.x * blockDim.x + threadIdx.x;
    if (e < NEDGE) {
        int dd = d_is64 ? (int)((const long long*)ei)[NEDGE + e]
                        : ((const int*)ei)[NEDGE + e];
        atomicAdd(&d_deg[dd], 1);
    }
}

// ---------------- k_scan: exclusive offsets -> cursor, invc ----------------
__global__ void __launch_bounds__(1024) k_scan() {
    __shared__ int wsum[32];
    int t = threadIdx.x, lane = t & 31, warp = t >> 5;
    int base = t * 32;
    int v[32];
    int s = 0;
#pragma unroll
    for (int i = 0; i < 32; i++) { v[i] = d_deg[base + i]; s += v[i]; }
    int sc = s;
#pragma unroll
    for (int o = 1; o < 32; o <<= 1) {
        int n = __shfl_up_sync(0xffffffffu, sc, o);
        if (lane >= o) sc += n;
    }
    if (lane == 31) wsum[warp] = sc;
    __syncthreads();
    if (warp == 0) {
        int ws = wsum[lane];
#pragma unroll
        for (int o = 1; o < 32; o <<= 1) {
            int n = __shfl_up_sync(0xffffffffu, ws, o);
            if (lane >= o) ws += n;
        }
        wsum[lane] = ws;
    }
    __syncthreads();
    int off = (warp > 0 ? wsum[warp - 1] : 0) + (sc - s);
#pragma unroll
    for (int i = 0; i < 32; i++) {
        d_cursor[base + i] = off;
        d_invc[base + i] = 1.0f / fmaxf((float)v[i], 1.0f);
        off += v[i];
    }
}

// ---------------- k_sortz: scatter sorted edges + zero agg ----------------
__global__ void __launch_bounds__(256) k_sortz(const void* __restrict__ ei) {
    int e = blockIdx.x * 256 + threadIdx.x;   // 524288 threads
    int is64 = d_is64;
    int ss, dd;
    if (is64) {
        ss = (int)((const long long*)ei)[e];
        dd = (int)((const long long*)ei)[NEDGE + e];
    } else {
        ss = ((const int*)ei)[e];
        dd = ((const int*)ei)[NEDGE + e];
    }
    int p = atomicAdd(&d_cursor[dd], 1);
    d_ssrc[p] = ss;
    d_sdst[p] = dd;
    ((float4*)d_agg)[e] = make_float4(0.f, 0.f, 0.f, 0.f);
    ((float4*)d_agg)[e + NEDGE] = make_float4(0.f, 0.f, 0.f, 0.f);
}

// ---------------- k_lift: mma tf32, 128 items/block ----------------
#define LIFT_IN   0
#define LIFT_B2   3072
#define LIFT_TS   3328
#define LIFT_WS   (3328 + 34816)
#define LIFT_SMEM (LIFT_WS + 18432)

__global__ void __launch_bounds__(256) k_lift(
    const float* __restrict__ x, const float* __restrict__ pos,
    const float* __restrict__ w1, const float* __restrict__ b1,
    const float* __restrict__ w2, const float* __restrict__ b2)
{
    extern __shared__ char smem[];
    float*    in_s = (float*)(smem + LIFT_IN);       // [128][6]
    float*    b2_s = (float*)(smem + LIFT_B2);
    uint32_t* t_s  = (uint32_t*)(smem + LIFT_TS);    // [128][68]
    float*    t_sf = (float*)(smem + LIFT_TS);
    uint32_t* w_s  = (uint32_t*)(smem + LIFT_WS);    // [64][72]

    int t = threadIdx.x;
    int item0 = blockIdx.x * 128;

    for (int idx = t; idx < 640; idx += 256) {
        int j = idx / 5, i = idx % 5;
        int item = item0 + j;
        int b = item >> 15, n = item & (NPTS - 1);
        in_s[j * 6 + i] = (i < 3) ? x[((size_t)b * NPTS + n) * 3 + i] : pos[n * 2 + (i - 3)];
    }
    if (t < 64) b2_s[t] = b2[t];
    __syncthreads();

    int c  = t & 63, jg = t >> 6;
    int w  = t >> 5, lane = t & 31;
    int r  = lane >> 2, c4 = lane & 3;
    int m0 = w * 16;

    float acc[8][4];
#pragma unroll
    for (int j = 0; j < 8; j++)
        acc[j][0] = acc[j][1] = acc[j][2] = acc[j][3] = 0.f;

    for (int ch = 0; ch < 4; ch++) {
        int cc = ch * 64 + c;
        float w0 = w1[cc], wA = w1[LIFTD + cc], wB = w1[2 * LIFTD + cc];
        float wC = w1[3 * LIFTD + cc], wD = w1[4 * LIFTD + cc];
        float bc = b1[cc];
#pragma unroll 4
        for (int rr = 0; rr < 32; rr++) {
            int row = jg * 32 + rr;
            const float* in = in_s + row * 6;
            float v = bc + in[0] * w0 + in[1] * wA + in[2] * wB + in[3] * wC + in[4] * wD;
            t_s[row * G_STRIDE + c] = f2tf32(gelu_f(v));
        }
        for (int idx = t; idx < 4096; idx += 256) {
            int k = idx >> 6, n = idx & 63;
            w_s[k * W_STRIDE + n] = f2tf32(w2[(ch * 64 + k) * HID + n]);
        }
        __syncthreads();

#pragma unroll
        for (int kk = 0; kk < 8; kk++) {
            uint32_t a[4];
            a[0] = t_s[(m0 + r)     * G_STRIDE + kk * 8 + c4];
            a[1] = t_s[(m0 + r + 8) * G_STRIDE + kk * 8 + c4];
            a[2] = t_s[(m0 + r)     * G_STRIDE + kk * 8 + c4 + 4];
            a[3] = t_s[(m0 + r + 8) * G_STRIDE + kk * 8 + c4 + 4];
#pragma unroll
            for (int j = 0; j < 8; j++) {
                uint32_t bb[2];
                bb[0] = w_s[(kk * 8 + c4)     * W_STRIDE + j * 8 + r];
                bb[1] = w_s[(kk * 8 + c4 + 4) * W_STRIDE + j * 8 + r];
                mma_tf32(acc[j], a, bb);
            }
        }
        __syncthreads();
    }

    // epilogue: C + b2 -> t_sf (warp-private rows), then linear store
#pragma unroll
    for (int j = 0; j < 8; j++) {
        int col = j * 8 + c4 * 2;
        float b0 = b2_s[col], b1v = b2_s[col + 1];
        *(float2*)(t_sf + (m0 + r)     * G_STRIDE + col) = make_float2(acc[j][0] + b0, acc[j][1] + b1v);
        *(float2*)(t_sf + (m0 + r + 8) * G_STRIDE + col) = make_float2(acc[j][2] + b0, acc[j][3] + b1v);
    }
    __syncthreads();
    for (int idx = t; idx < 8192; idx += 256) {
        int row = idx >> 6, cc = idx & 63;
        d_h[(size_t)(item0 + row) * 64 + cc] = t_sf[row * G_STRIDE + cc];
    }
}

// ---------------- k_APd: mma tf32, 128 items/block, + Pd ----------------
#define APD_POS  0
#define APD_PW   1024
#define APD_HS   2048
#define APD_WS   (2048 + 34816)
#define APD_SMEM (APD_WS + 18432)

__global__ void __launch_bounds__(256) k_APd(
    const float* __restrict__ pos, const float* __restrict__ kW1_l,
    const float* __restrict__ kb1_l)
{
    extern __shared__ char smem[];
    float*    pos_s = (float*)(smem + APD_POS);     // [128][2]
    float*    pw_s  = (float*)(smem + APD_PW);      // [4][64] = W1 rows 0..3
    uint32_t* h_s   = (uint32_t*)(smem + APD_HS);   // [128][68]
    float*    h_sf  = (float*)(smem + APD_HS);
    uint32_t* w_s   = (uint32_t*)(smem + APD_WS);   // [64][72]

    int t = threadIdx.x;
    int item0 = blockIdx.x * 128;

    if (t < 256) {
        int j = t >> 1, i = t & 1;
        int n = (item0 + j) & (NPTS - 1);
        pos_s[j * 2 + i] = pos[n * 2 + i];
    }
    if (t < 256) pw_s[t] = kW1_l[t];   // rows 0..3 of W1
    for (int idx = t; idx < 8192; idx += 256) {
        int row = idx >> 6, k = idx & 63;
        h_s[row * G_STRIDE + k] = f2tf32(d_h[(size_t)(item0 + row) * 64 + k]);
    }
    for (int idx = t; idx < 4096; idx += 256) {
        int k = idx >> 6, n = idx & 63;
        w_s[k * W_STRIDE + n] = f2tf32(kW1_l[(4 + k) * 64 + n]);
    }
    __syncthreads();

    // Pd for this n-range (blocks covering batch 0 span all n exactly once)
    if (item0 < NPTS) {
        for (int idx = t; idx < 8192; idx += 256) {
            int row = idx >> 6, cc = idx & 63;
            int n = item0 + row;
            d_Pd[(size_t)n * 64 + cc] = kb1_l[cc] + pos_s[row * 2] * pw_s[128 + cc]
                                                  + pos_s[row * 2 + 1] * pw_s[192 + cc];
        }
    }

    int w = t >> 5, lane = t & 31;
    int r = lane >> 2, c4 = lane & 3;
    int m0 = w * 16;

    float acc[8][4];
#pragma unroll
    for (int j = 0; j < 8; j++)
        acc[j][0] = acc[j][1] = acc[j][2] = acc[j][3] = 0.f;

#pragma unroll
    for (int kk = 0; kk < 8; kk++) {
        uint32_t a[4];
        a[0] = h_s[(m0 + r)     * G_STRIDE + kk * 8 + c4];
        a[1] = h_s[(m0 + r + 8) * G_STRIDE + kk * 8 + c4];
        a[2] = h_s[(m0 + r)     * G_STRIDE + kk * 8 + c4 + 4];
        a[3] = h_s[(m0 + r + 8) * G_STRIDE + kk * 8 + c4 + 4];
#pragma unroll
        for (int j = 0; j < 8; j++) {
            uint32_t bb[2];
            bb[0] = w_s[(kk * 8 + c4)     * W_STRIDE + j * 8 + r];
            bb[1] = w_s[(kk * 8 + c4 + 4) * W_STRIDE + j * 8 + r];
            mma_tf32(acc[j], a, bb);
        }
    }
    __syncthreads();

    // epilogue: add pos terms, stage, store
    float p00 = pos_s[(m0 + r) * 2],     p01 = pos_s[(m0 + r) * 2 + 1];
    float p10 = pos_s[(m0 + r + 8) * 2], p11 = pos_s[(m0 + r + 8) * 2 + 1];
#pragma unroll
    for (int j = 0; j < 8; j++) {
        int col = j * 8 + c4 * 2;
        float w00 = pw_s[col], w01 = pw_s[col + 1];
        float w10 = pw_s[64 + col], w11 = pw_s[64 + col + 1];
        *(float2*)(h_sf + (m0 + r) * G_STRIDE + col) =
            make_float2(acc[j][0] + p00 * w00 + p01 * w10, acc[j][1] + p00 * w01 + p01 * w11);
        *(float2*)(h_sf + (m0 + r + 8) * G_STRIDE + col) =
            make_float2(acc[j][2] + p10 * w00 + p11 * w10, acc[j][3] + p10 * w01 + p11 * w11);
    }
    __syncthreads();
    for (int idx = t; idx < 8192; idx += 256) {
        int row = idx >> 6, cc = idx & 63;
        d_A[(size_t)(item0 + row) * 64 + cc] = h_sf[row * G_STRIDE + cc];
    }
}

// ---------------- k_edge: mma tf32, sorted edges, run-scatter ----------------
#define G_BYTES  (128 * G_STRIDE * 4)
#define W_BYTES  (64 * W_STRIDE * 4)
#define EDGE_SMEM (G_BYTES + W_BYTES + 256 + 1024)

__global__ void __launch_bounds__(256) k_edge(
    const float* __restrict__ kW2_l, const float* __restrict__ kb2_l)
{
    extern __shared__ char smem[];
    uint32_t* g_s    = (uint32_t*)smem;
    float*    g_sf   = (float*)smem;
    uint32_t* w_s    = (uint32_t*)(smem + G_BYTES);
    float*    bias_s = (float*)(smem + G_BYTES + W_BYTES);
    int*      src_s  = (int*)(smem + G_BYTES + W_BYTES + 256);
    int*      dst_s  = (int*)(smem + G_BYTES + W_BYTES + 768);

    int t = threadIdx.x;
    int e_base = blockIdx.x * 128;

#pragma unroll
    for (int rr = 0; rr < 16; rr++) {
        int i = t + 256 * rr;
        w_s[(i >> 6) * W_STRIDE + (i & 63)] = f2tf32(kW2_l[i]);
    }
    if (t < 128) {
        src_s[t] = d_ssrc[e_base + t];
        dst_s[t] = d_sdst[e_base + t];
    }
    if (t < 64) bias_s[t] = kb2_l[t];
    __syncthreads();

    int c  = t & 63, eg = t >> 6;
    int w  = t >> 5, lane = t & 31;
    int r  = lane >> 2, c4 = lane & 3;
    int m0 = w * 16;
    int ci4 = (t & 15) * 4;       // scatter: 16 col groups x float4
    int e0  = (t >> 4) * 8;       // 16 edge groups x 8 edges

    for (int b = 0; b < NBATCH; b++) {
        const float* Ab = d_A + (size_t)b * NPTS * 64;

#pragma unroll 4
        for (int rr = 0; rr < 32; rr++) {
            int e = eg * 32 + rr;
            float v = Ab[(size_t)src_s[e] * 64 + c] + d_Pd[(size_t)dst_s[e] * 64 + c];
            g_s[e * G_STRIDE + c] = f2tf32(gelu_f(v));
        }
        __syncthreads();

        float acc[8][4];
#pragma unroll
        for (int j = 0; j < 8; j++) {
            float b0 = bias_s[j * 8 + c4 * 2];
            float b1 = bias_s[j * 8 + c4 * 2 + 1];
            acc[j][0] = b0; acc[j][1] = b1; acc[j][2] = b0; acc[j][3] = b1;
        }
#pragma unroll
        for (int kk = 0; kk < 8; kk++) {
            uint32_t a[4];
            a[0] = g_s[(m0 + r)     * G_STRIDE + kk * 8 + c4];
            a[1] = g_s[(m0 + r + 8) * G_STRIDE + kk * 8 + c4];
            a[2] = g_s[(m0 + r)     * G_STRIDE + kk * 8 + c4 + 4];
            a[3] = g_s[(m0 + r + 8) * G_STRIDE + kk * 8 + c4 + 4];
#pragma unroll
            for (int j = 0; j < 8; j++) {
                uint32_t bb[2];
                bb[0] = w_s[(kk * 8 + c4)     * W_STRIDE + j * 8 + r];
                bb[1] = w_s[(kk * 8 + c4 + 4) * W_STRIDE + j * 8 + r];
                mma_tf32(acc[j], a, bb);
            }
        }

        // stage C (warp-private rows)
#pragma unroll
        for (int j = 0; j < 8; j++) {
            *(float2*)(g_sf + (m0 + r)     * G_STRIDE + j * 8 + c4 * 2) =
                make_float2(acc[j][0], acc[j][1]);
            *(float2*)(g_sf + (m0 + r + 8) * G_STRIDE + j * 8 + c4 * 2) =
                make_float2(acc[j][2], acc[j][3]);
        }
        __syncthreads();

        // run-accumulated scatter over sorted dst
        {
            float* aggb = d_agg + (size_t)b * NPTS * 64;
            int cur = dst_s[e0];
            float4 a4 = *(const float4*)(g_sf + e0 * G_STRIDE + ci4);
#pragma unroll
            for (int i = 1; i < 8; i++) {
                int e = e0 + i;
                int dd = dst_s[e];
                float4 v = *(const float4*)(g_sf + e * G_STRIDE + ci4);
                if (dd != cur) {
                    red4(aggb + (size_t)cur * 64 + ci4, a4);
                    a4 = v; cur = dd;
                } else {
                    a4.x += v.x; a4.y += v.y; a4.z += v.z; a4.w += v.w;
                }
            }
            red4(aggb + (size_t)cur * 64 + ci4, a4);
        }
        __syncthreads();
    }
}

// ---------------- update ----------------
__global__ void __launch_bounds__(256) k_update() {
    int i = blockIdx.x * 256 + threadIdx.x;
    int item = i >> 4;
    int n = item & (NPTS - 1);
    float ic = d_invc[n];
    float4 h = ((float4*)d_h)[i];
    float4 a = ((float4*)d_agg)[i];
    h.x += a.x * ic; h.y += a.y * ic; h.z += a.z * ic; h.w += a.w * ic;
    ((float4*)d_h)[i] = h;
    ((float4*)d_agg)[i] = make_float4(0.f, 0.f, 0.f, 0.f);
}

// ---------------- k_proj: mma tf32 phase1 + dot epilogue ----------------
#define PROJ_HS   0
#define PROJ_WS   34816
#define PROJ_W2   (34816 + 18432)
#define PROJ_B1   (PROJ_W2 + 1024)
#define PROJ_SMEM (PROJ_B1 + 1024)

__global__ void __launch_bounds__(256) k_proj(
    const float* __restrict__ w1, const float* __restrict__ b1,
    const float* __restrict__ w2, const float* __restrict__ b2,
    float* __restrict__ out)
{
    extern __shared__ char smem[];
    uint32_t* h_s  = (uint32_t*)(smem + PROJ_HS);   // [128][68]
    uint32_t* w_s  = (uint32_t*)(smem + PROJ_WS);   // [64][72]
    float*    w2_s = (float*)(smem + PROJ_W2);      // [256]
    float*    b1_s = (float*)(smem + PROJ_B1);      // [256]

    int t = threadIdx.x;
    int item0 = blockIdx.x * 128;

    for (int idx = t; idx < 8192; idx += 256) {
        int row = idx >> 6, k = idx & 63;
        h_s[row * G_STRIDE + k] = f2tf32(d_h[(size_t)(item0 + row) * 64 + k]);
    }
    w2_s[t] = w2[t];
    b1_s[t] = b1[t];
    __syncthreads();

    int w = t >> 5, lane = t & 31;
    int r = lane >> 2, c4 = lane & 3;
    int m0 = w * 16;

    uint32_t a[8][4];
#pragma unroll
    for (int kk = 0; kk < 8; kk++) {
        a[kk][0] = h_s[(m0 + r)     * G_STRIDE + kk * 8 + c4];
        a[kk][1] = h_s[(m0 + r + 8) * G_STRIDE + kk * 8 + c4];
        a[kk][2] = h_s[(m0 + r)     * G_STRIDE + kk * 8 + c4 + 4];
        a[kk][3] = h_s[(m0 + r + 8) * G_STRIDE + kk * 8 + c4 + 4];
    }

    float sum0 = 0.f, sum1 = 0.f;
    for (int ch = 0; ch < 4; ch++) {
        __syncthreads();   // protect w_s from previous chunk use
        for (int idx = t; idx < 4096; idx += 256) {
            int k = idx >> 6, n = idx & 63;
            w_s[k * W_STRIDE + n] = f2tf32(w1[k * 256 + ch * 64 + n]);
        }
        __syncthreads();

        float acc[8][4];
#pragma unroll
        for (int j = 0; j < 8; j++)
            acc[j][0] = acc[j][1] = acc[j][2] = acc[j][3] = 0.f;
#pragma unroll
        for (int kk = 0; kk < 8; kk++) {
#pragma unroll
            for (int j = 0; j < 8; j++) {
                uint32_t bb[2];
                bb[0] = w_s[(kk * 8 + c4)     * W_STRIDE + j * 8 + r];
                bb[1] = w_s[(kk * 8 + c4 + 4) * W_STRIDE + j * 8 + r];
                mma_tf32(acc[j], a[kk], bb);
            }
        }
#pragma unroll
        for (int j = 0; j < 8; j++) {
            int col = ch * 64 + j * 8 + c4 * 2;
            sum0 += gelu_f(acc[j][0] + b1_s[col]) * w2_s[col]
                  + gelu_f(acc[j][1] + b1_s[col + 1]) * w2_s[col + 1];
            sum1 += gelu_f(acc[j][2] + b1_s[col]) * w2_s[col]
                  + gelu_f(acc[j][3] + b1_s[col + 1]) * w2_s[col + 1];
        }
    }

    // reduce over the 4 lanes of each quad (same r, c4 = 0..3)
    sum0 += __shfl_xor_sync(0xffffffffu, sum0, 1);
    sum0 += __shfl_xor_sync(0xffffffffu, sum0, 2);
    sum1 += __shfl_xor_sync(0xffffffffu, sum1, 1);
    sum1 += __shfl_xor_sync(0xffffffffu, sum1, 2);
    if (c4 == 0) {
        float bb = b2[0];
        out[item0 + m0 + r]     = sum0 + bb;
        out[item0 + m0 + r + 8] = sum1 + bb;
    }
}

// ---------------- launch ----------------
extern "C" void kernel_launch(void* const* d_in, const int* in_sizes, int n_in,
                              void* d_out, int out_size) {
    (void)in_sizes; (void)n_in; (void)out_size;
    const float* x    = (const float*)d_in[0];
    const float* pos  = (const float*)d_in[1];
    const void*  ei   = d_in[2];
    const float* lw1  = (const float*)d_in[3];
    const float* lb1  = (const float*)d_in[4];
    const float* lw2  = (const float*)d_in[5];
    const float* lb2  = (const float*)d_in[6];
    const float* kW1  = (const float*)d_in[7];
    const float* kb1  = (const float*)d_in[8];
    const float* kW2  = (const float*)d_in[9];
    const float* kb2  = (const float*)d_in[10];
    const float* pw1  = (const float*)d_in[11];
    const float* pb1  = (const float*)d_in[12];
    const float* pw2  = (const float*)d_in[13];
    const float* pb2  = (const float*)d_in[14];
    float* out = (float*)d_out;

    cudaFuncSetAttribute(k_lift, cudaFuncAttributeMaxDynamicSharedMemorySize, LIFT_SMEM);
    cudaFuncSetAttribute(k_APd,  cudaFuncAttributeMaxDynamicSharedMemorySize, APD_SMEM);
    cudaFuncSetAttribute(k_edge, cudaFuncAttributeMaxDynamicSharedMemorySize, EDGE_SMEM);
    cudaFuncSetAttribute(k_proj, cudaFuncAttributeMaxDynamicSharedMemorySize, PROJ_SMEM);

    k_detect<<<1, 256>>>(ei);                                        // 0
    k_count<<<NEDGE / 256, 256>>>(ei);                               // 1
    k_scan<<<1, 1024>>>();                                           // 2
    k_sortz<<<NEDGE / 256, 256>>>(ei);                               // 3
    k_lift<<<(NBATCH * NPTS) / 128, 256, LIFT_SMEM>>>(x, pos, lw1, lb1, lw2, lb2);  // 4

    for (int l = 0; l < NLAYER; l++) {
        const float* W1l = kW1 + (size_t)l * 68 * 64;
        const float* b1l = kb1 + (size_t)l * 64;
        const float* W2l = kW2 + (size_t)l * 64 * 64;
        const float* b2l = kb2 + (size_t)l * 64;
        k_APd<<<(NBATCH * NPTS) / 128, 256, APD_SMEM>>>(pos, W1l, b1l);   // 5,8,11,14
        k_edge<<<NEDGE / 128, 256, EDGE_SMEM>>>(W2l, b2l);                // 6,9,12,15
        k_update<<<4096, 256>>>();                                        // 7,10,13,16
    }

    k_proj<<<(NBATCH * NPTS) / 128, 256, PROJ_SMEM>>>(pw1, pb1, pw2, pb2, out);  // 17
}

// round 5
// speedup vs baseline: 3.1354x; 1.1898x over previous
#include <cuda_runtime.h>
#include <cuda_fp16.h>
#include <math.h>
#include <stdint.h>

#define NPTS   32768
#define NEDGE  524288
#define NBATCH 2
#define HID    64
#define LIFTD  256
#define NLAYER 4

// ---------------- scratch ----------------
__device__ float d_h[NBATCH * NPTS * HID];
__device__ float d_A[NBATCH * NPTS * HID];
__device__ float d_Pd[NPTS * HID];
__device__ float d_agg[NBATCH * NPTS * HID];
__device__ float d_invc[NPTS];
__device__ int   d_deg[NPTS];
__device__ int   d_cursor[NPTS];
__device__ int   d_ssrc[NEDGE];
__device__ int   d_sdst[NEDGE];
__device__ int   d_is64;

__device__ __forceinline__ float gelu_f(float v) {
    return 0.5f * v * (1.0f + erff(v * 0.70710678118654752f));
}
__device__ __forceinline__ uint32_t f2tf32(float f) {
    uint32_t r;
    asm("cvt.rna.tf32.f32 %0, %1;" : "=r"(r) : "f"(f));
    return r;
}
__device__ __forceinline__ void mma_tf32(float* d, const uint32_t* a, const uint32_t* b) {
    asm volatile("mma.sync.aligned.m16n8k8.row.col.f32.tf32.tf32.f32 "
                 "{%0,%1,%2,%3}, {%4,%5,%6,%7}, {%8,%9}, {%0,%1,%2,%3};"
                 : "+f"(d[0]), "+f"(d[1]), "+f"(d[2]), "+f"(d[3])
                 : "r"(a[0]), "r"(a[1]), "r"(a[2]), "r"(a[3]), "r"(b[0]), "r"(b[1]));
}
__device__ __forceinline__ void mma_fp16(float* d, const uint32_t* a, const uint32_t* b) {
    asm volatile("mma.sync.aligned.m16n8k16.row.col.f32.f16.f16.f32 "
                 "{%0,%1,%2,%3}, {%4,%5,%6,%7}, {%8,%9}, {%0,%1,%2,%3};"
                 : "+f"(d[0]), "+f"(d[1]), "+f"(d[2]), "+f"(d[3])
                 : "r"(a[0]), "r"(a[1]), "r"(a[2]), "r"(a[3]), "r"(b[0]), "r"(b[1]));
}
__device__ __forceinline__ void red4(float* p, float4 v) {
    asm volatile("red.global.add.v4.f32 [%0], {%1,%2,%3,%4};" ::
                 "l"(p), "f"(v.x), "f"(v.y), "f"(v.z), "f"(v.w) : "memory");
}
__device__ __forceinline__ uint32_t pack_h2(float a, float b) {
    __half2 h = __floats2half2_rn(a, b);
    return *(uint32_t*)&h;
}

#define G_STRIDE 68
#define W_STRIDE 72

// ---------------- k_detect: zero deg + dtype detect ----------------
__global__ void __launch_bounds__(256) k_detect(const void* __restrict__ ei) {
    int t = threadIdx.x;
#pragma unroll
    for (int r = 0; r < 32; r++)
        ((int4*)d_deg)[t + 256 * r] = make_int4(0, 0, 0, 0);
    __shared__ int bad;
    if (t == 0) bad = 0;
    __syncthreads();
    if (t < 128) {
        long long v = ((const long long*)ei)[t];
        if (v < 0 || v >= NPTS) atomicOr(&bad, 1);
    }
    __syncthreads();
    if (t == 0) d_is64 = bad ? 0 : 1;
}

// ---------------- k_count ----------------
__global__ void k_count(const void* __restrict__ ei) {
    int e = blockIdx.x * blockDim.x + threadIdx.x;
    if (e < NEDGE) {
        int dd = d_is64 ? (int)((const long long*)ei)[NEDGE + e]
                        : ((const int*)ei)[NEDGE + e];
        atomicAdd(&d_deg[dd], 1);
    }
}

// ---------------- k_scan ----------------
__global__ void __launch_bounds__(1024) k_scan() {
    __shared__ int wsum[32];
    int t = threadIdx.x, lane = t & 31, warp = t >> 5;
    int base = t * 32;
    int v[32];
    int s = 0;
#pragma unroll
    for (int i = 0; i < 32; i++) { v[i] = d_deg[base + i]; s += v[i]; }
    int sc = s;
#pragma unroll
    for (int o = 1; o < 32; o <<= 1) {
        int n = __shfl_up_sync(0xffffffffu, sc, o);
        if (lane >= o) sc += n;
    }
    if (lane == 31) wsum[warp] = sc;
    __syncthreads();
    if (warp == 0) {
        int ws = wsum[lane];
#pragma unroll
        for (int o = 1; o < 32; o <<= 1) {
            int n = __shfl_up_sync(0xffffffffu, ws, o);
            if (lane >= o) ws += n;
        }
        wsum[lane] = ws;
    }
    __syncthreads();
    int off = (warp > 0 ? wsum[warp - 1] : 0) + (sc - s);
#pragma unroll
    for (int i = 0; i < 32; i++) {
        d_cursor[base + i] = off;
        d_invc[base + i] = 1.0f / fmaxf((float)v[i], 1.0f);
        off += v[i];
    }
}

// ---------------- k_sortz: scatter sorted edges + zero agg ----------------
__global__ void __launch_bounds__(256) k_sortz(const void* __restrict__ ei) {
    int e = blockIdx.x * 256 + threadIdx.x;
    int is64 = d_is64;
    int ss, dd;
    if (is64) {
        ss = (int)((const long long*)ei)[e];
        dd = (int)((const long long*)ei)[NEDGE + e];
    } else {
        ss = ((const int*)ei)[e];
        dd = ((const int*)ei)[NEDGE + e];
    }
    int p = atomicAdd(&d_cursor[dd], 1);
    d_ssrc[p] = ss;
    d_sdst[p] = dd;
    ((float4*)d_agg)[e] = make_float4(0.f, 0.f, 0.f, 0.f);
    ((float4*)d_agg)[e + NEDGE] = make_float4(0.f, 0.f, 0.f, 0.f);
}

// ---------------- k_lift: mma tf32, 128 items/block ----------------
#define LIFT_IN   0
#define LIFT_B2   3072
#define LIFT_TS   3328
#define LIFT_WS   (3328 + 34816)
#define LIFT_SMEM (LIFT_WS + 18432)

__global__ void __launch_bounds__(256) k_lift(
    const float* __restrict__ x, const float* __restrict__ pos,
    const float* __restrict__ w1, const float* __restrict__ b1,
    const float* __restrict__ w2, const float* __restrict__ b2)
{
    extern __shared__ char smem[];
    float*    in_s = (float*)(smem + LIFT_IN);
    float*    b2_s = (float*)(smem + LIFT_B2);
    uint32_t* t_s  = (uint32_t*)(smem + LIFT_TS);
    float*    t_sf = (float*)(smem + LIFT_TS);
    uint32_t* w_s  = (uint32_t*)(smem + LIFT_WS);

    int t = threadIdx.x;
    int item0 = blockIdx.x * 128;

    for (int idx = t; idx < 640; idx += 256) {
        int j = idx / 5, i = idx % 5;
        int item = item0 + j;
        int b = item >> 15, n = item & (NPTS - 1);
        in_s[j * 6 + i] = (i < 3) ? x[((size_t)b * NPTS + n) * 3 + i] : pos[n * 2 + (i - 3)];
    }
    if (t < 64) b2_s[t] = b2[t];
    __syncthreads();

    int c  = t & 63, jg = t >> 6;
    int w  = t >> 5, lane = t & 31;
    int r  = lane >> 2, c4 = lane & 3;
    int m0 = w * 16;

    float acc[8][4];
#pragma unroll
    for (int j = 0; j < 8; j++)
        acc[j][0] = acc[j][1] = acc[j][2] = acc[j][3] = 0.f;

    for (int ch = 0; ch < 4; ch++) {
        int cc = ch * 64 + c;
        float w0 = w1[cc], wA = w1[LIFTD + cc], wB = w1[2 * LIFTD + cc];
        float wC = w1[3 * LIFTD + cc], wD = w1[4 * LIFTD + cc];
        float bc = b1[cc];
#pragma unroll 4
        for (int rr = 0; rr < 32; rr++) {
            int row = jg * 32 + rr;
            const float* in = in_s + row * 6;
            float v = bc + in[0] * w0 + in[1] * wA + in[2] * wB + in[3] * wC + in[4] * wD;
            t_s[row * G_STRIDE + c] = f2tf32(gelu_f(v));
        }
        for (int idx = t; idx < 4096; idx += 256) {
            int k = idx >> 6, n = idx & 63;
            w_s[k * W_STRIDE + n] = f2tf32(w2[(ch * 64 + k) * HID + n]);
        }
        __syncthreads();

#pragma unroll
        for (int kk = 0; kk < 8; kk++) {
            uint32_t a[4];
            a[0] = t_s[(m0 + r)     * G_STRIDE + kk * 8 + c4];
            a[1] = t_s[(m0 + r + 8) * G_STRIDE + kk * 8 + c4];
            a[2] = t_s[(m0 + r)     * G_STRIDE + kk * 8 + c4 + 4];
            a[3] = t_s[(m0 + r + 8) * G_STRIDE + kk * 8 + c4 + 4];
#pragma unroll
            for (int j = 0; j < 8; j++) {
                uint32_t bb[2];
                bb[0] = w_s[(kk * 8 + c4)     * W_STRIDE + j * 8 + r];
                bb[1] = w_s[(kk * 8 + c4 + 4) * W_STRIDE + j * 8 + r];
                mma_tf32(acc[j], a, bb);
            }
        }
        __syncthreads();
    }

#pragma unroll
    for (int j = 0; j < 8; j++) {
        int col = j * 8 + c4 * 2;
        float b0 = b2_s[col], b1v = b2_s[col + 1];
        *(float2*)(t_sf + (m0 + r)     * G_STRIDE + col) = make_float2(acc[j][0] + b0, acc[j][1] + b1v);
        *(float2*)(t_sf + (m0 + r + 8) * G_STRIDE + col) = make_float2(acc[j][2] + b0, acc[j][3] + b1v);
    }
    __syncthreads();
    for (int idx = t; idx < 8192; idx += 256) {
        int row = idx >> 6, cc = idx & 63;
        d_h[(size_t)(item0 + row) * 64 + cc] = t_sf[row * G_STRIDE + cc];
    }
}

// ---------------- k_APd: fused update + mma tf32 + Pd ----------------
#define APD_POS  0
#define APD_PW   1024
#define APD_HS   2048
#define APD_WS   (2048 + 34816)
#define APD_SMEM (APD_WS + 18432)

__global__ void __launch_bounds__(256) k_APd(
    const float* __restrict__ pos, const float* __restrict__ kW1_l,
    const float* __restrict__ kb1_l, int do_upd)
{
    extern __shared__ char smem[];
    float*    pos_s = (float*)(smem + APD_POS);
    float*    pw_s  = (float*)(smem + APD_PW);
    uint32_t* h_s   = (uint32_t*)(smem + APD_HS);
    float*    h_sf  = (float*)(smem + APD_HS);
    uint32_t* w_s   = (uint32_t*)(smem + APD_WS);

    int t = threadIdx.x;
    int item0 = blockIdx.x * 128;

    if (t < 256) {
        int j = t >> 1, i = t & 1;
        int n = (item0 + j) & (NPTS - 1);
        pos_s[j * 2 + i] = pos[n * 2 + i];
    }
    if (t < 256) pw_s[t] = kW1_l[t];

    // fused update: h_new = h + agg*invc; write back; zero agg; stage tf32
    if (do_upd) {
        for (int idx = t; idx < 8192; idx += 256) {
            int row = idx >> 6, k = idx & 63;
            size_t gi = (size_t)(item0 + row) * 64 + k;
            float ic = d_invc[(item0 + row) & (NPTS - 1)];
            float v = d_h[gi] + d_agg[gi] * ic;
            d_h[gi] = v;
            d_agg[gi] = 0.f;
            h_s[row * G_STRIDE + k] = f2tf32(v);
        }
    } else {
        for (int idx = t; idx < 8192; idx += 256) {
            int row = idx >> 6, k = idx & 63;
            h_s[row * G_STRIDE + k] = f2tf32(d_h[(size_t)(item0 + row) * 64 + k]);
        }
    }
    for (int idx = t; idx < 4096; idx += 256) {
        int k = idx >> 6, n = idx & 63;
        w_s[k * W_STRIDE + n] = f2tf32(kW1_l[(4 + k) * 64 + n]);
    }
    __syncthreads();

    if (item0 < NPTS) {
        for (int idx = t; idx < 8192; idx += 256) {
            int row = idx >> 6, cc = idx & 63;
            int n = item0 + row;
            d_Pd[(size_t)n * 64 + cc] = kb1_l[cc] + pos_s[row * 2] * pw_s[128 + cc]
                                                  + pos_s[row * 2 + 1] * pw_s[192 + cc];
        }
    }

    int w = t >> 5, lane = t & 31;
    int r = lane >> 2, c4 = lane & 3;
    int m0 = w * 16;

    float acc[8][4];
#pragma unroll
    for (int j = 0; j < 8; j++)
        acc[j][0] = acc[j][1] = acc[j][2] = acc[j][3] = 0.f;

#pragma unroll
    for (int kk = 0; kk < 8; kk++) {
        uint32_t a[4];
        a[0] = h_s[(m0 + r)     * G_STRIDE + kk * 8 + c4];
        a[1] = h_s[(m0 + r + 8) * G_STRIDE + kk * 8 + c4];
        a[2] = h_s[(m0 + r)     * G_STRIDE + kk * 8 + c4 + 4];
        a[3] = h_s[(m0 + r + 8) * G_STRIDE + kk * 8 + c4 + 4];
#pragma unroll
        for (int j = 0; j < 8; j++) {
            uint32_t bb[2];
            bb[0] = w_s[(kk * 8 + c4)     * W_STRIDE + j * 8 + r];
            bb[1] = w_s[(kk * 8 + c4 + 4) * W_STRIDE + j * 8 + r];
            mma_tf32(acc[j], a, bb);
        }
    }
    __syncthreads();

    float p00 = pos_s[(m0 + r) * 2],     p01 = pos_s[(m0 + r) * 2 + 1];
    float p10 = pos_s[(m0 + r + 8) * 2], p11 = pos_s[(m0 + r + 8) * 2 + 1];
#pragma unroll
    for (int j = 0; j < 8; j++) {
        int col = j * 8 + c4 * 2;
        float w00 = pw_s[col], w01 = pw_s[col + 1];
        float w10 = pw_s[64 + col], w11 = pw_s[64 + col + 1];
        *(float2*)(h_sf + (m0 + r) * G_STRIDE + col) =
            make_float2(acc[j][0] + p00 * w00 + p01 * w10, acc[j][1] + p00 * w01 + p01 * w11);
        *(float2*)(h_sf + (m0 + r + 8) * G_STRIDE + col) =
            make_float2(acc[j][2] + p10 * w00 + p11 * w10, acc[j][3] + p10 * w01 + p11 * w11);
    }
    __syncthreads();
    for (int idx = t; idx < 8192; idx += 256) {
        int row = idx >> 6, cc = idx & 63;
        d_A[(size_t)(item0 + row) * 64 + cc] = h_sf[row * G_STRIDE + cc];
    }
}

// ---------------- k_edge: fp16 mma m16n8k16, sorted edges ----------------
// smem: g (128x36 u32 half2, stride 144B), W packed half2 (32x72 u32),
//       C staging (128x68 f32), bias, src, dst
#define EG_OFF   0
#define EW_OFF   18432
#define EC_OFF   27648
#define EB_OFF   62464
#define ES_OFF   62720
#define ED_OFF   63232
#define EDGE_SMEM 63744
#define GH_STRIDE 36
#define C_STRIDE  68

__global__ void __launch_bounds__(256) k_edge(
    const float* __restrict__ kW2_l, const float* __restrict__ kb2_l)
{
    extern __shared__ char smem[];
    uint32_t* g_s    = (uint32_t*)(smem + EG_OFF);
    uint32_t* w_s    = (uint32_t*)(smem + EW_OFF);
    float*    c_s    = (float*)(smem + EC_OFF);
    float*    bias_s = (float*)(smem + EB_OFF);
    int*      src_s  = (int*)(smem + ES_OFF);
    int*      dst_s  = (int*)(smem + ED_OFF);

    int t = threadIdx.x;
    int e_base = blockIdx.x * 128;

    // stage W2 as packed half2: w_s[i*72 + n] = (W[2i][n], W[2i+1][n])
    for (int idx = t; idx < 2048; idx += 256) {
        int i = idx >> 6, n = idx & 63;
        w_s[i * W_STRIDE + n] = pack_h2(kW2_l[(2 * i) * 64 + n], kW2_l[(2 * i + 1) * 64 + n]);
    }
    if (t < 128) {
        src_s[t] = d_ssrc[e_base + t];
        dst_s[t] = d_sdst[e_base + t];
    }
    if (t < 64) bias_s[t] = kb2_l[t];
    __syncthreads();

    int h2i = t & 31, eg = t >> 5;     // phase1: half2 index, warp edge group
    int w  = t >> 5, lane = t & 31;
    int r  = lane >> 2, c4 = lane & 3;
    int m0 = w * 16;
    int ci4 = (t & 15) * 4;
    int e0  = (t >> 4) * 8;

    for (int b = 0; b < NBATCH; b++) {
        const float* Ab = d_A + (size_t)b * NPTS * 64;

        // phase 1: g[e][c] = fp16(gelu(A[src]+Pd[dst])), 2 channels/thread
#pragma unroll 4
        for (int i = 0; i < 16; i++) {
            int e = eg * 16 + i;
            float2 va = *(const float2*)(Ab + (size_t)src_s[e] * 64 + h2i * 2);
            float2 vp = *(const float2*)(d_Pd + (size_t)dst_s[e] * 64 + h2i * 2);
            g_s[e * GH_STRIDE + h2i] = pack_h2(gelu_f(va.x + vp.x), gelu_f(va.y + vp.y));
        }
        __syncthreads();

        // phase 2: fp16 mma, warp tile 16 edges x 64 cols, K=64 in 4 steps
        float acc[8][4];
#pragma unroll
        for (int j = 0; j < 8; j++) {
            float b0 = bias_s[j * 8 + c4 * 2];
            float b1 = bias_s[j * 8 + c4 * 2 + 1];
            acc[j][0] = b0; acc[j][1] = b1; acc[j][2] = b0; acc[j][3] = b1;
        }
#pragma unroll
        for (int kk = 0; kk < 4; kk++) {
            uint32_t a[4];
            a[0] = g_s[(m0 + r)     * GH_STRIDE + kk * 8 + c4];
            a[1] = g_s[(m0 + r + 8) * GH_STRIDE + kk * 8 + c4];
            a[2] = g_s[(m0 + r)     * GH_STRIDE + kk * 8 + c4 + 4];
            a[3] = g_s[(m0 + r + 8) * GH_STRIDE + kk * 8 + c4 + 4];
#pragma unroll
            for (int j = 0; j < 8; j++) {
                uint32_t bb[2];
                bb[0] = w_s[(kk * 8 + c4)     * W_STRIDE + j * 8 + r];
                bb[1] = w_s[(kk * 8 + c4 + 4) * W_STRIDE + j * 8 + r];
                mma_fp16(acc[j], a, bb);
            }
        }

        // stage C (warp-private rows of c_s)
#pragma unroll
        for (int j = 0; j < 8; j++) {
            *(float2*)(c_s + (m0 + r)     * C_STRIDE + j * 8 + c4 * 2) =
                make_float2(acc[j][0], acc[j][1]);
            *(float2*)(c_s + (m0 + r + 8) * C_STRIDE + j * 8 + c4 * 2) =
                make_float2(acc[j][2], acc[j][3]);
        }
        __syncthreads();

        // run-accumulated scatter (sorted dst)
        {
            float* aggb = d_agg + (size_t)b * NPTS * 64;
            int cur = dst_s[e0];
            float4 a4 = *(const float4*)(c_s + e0 * C_STRIDE + ci4);
#pragma unroll
            for (int i = 1; i < 8; i++) {
                int e = e0 + i;
                int dd = dst_s[e];
                float4 v = *(const float4*)(c_s + e * C_STRIDE + ci4);
                if (dd != cur) {
                    red4(aggb + (size_t)cur * 64 + ci4, a4);
                    a4 = v; cur = dd;
                } else {
                    a4.x += v.x; a4.y += v.y; a4.z += v.z; a4.w += v.w;
                }
            }
            red4(aggb + (size_t)cur * 64 + ci4, a4);
        }
    }
}

// ---------------- k_proj: fused final update + mma tf32 ----------------
#define PROJ_HS   0
#define PROJ_WS   34816
#define PROJ_W2   (34816 + 18432)
#define PROJ_B1   (PROJ_W2 + 1024)
#define PROJ_SMEM (PROJ_B1 + 1024)

__global__ void __launch_bounds__(256) k_proj(
    const float* __restrict__ w1, const float* __restrict__ b1,
    const float* __restrict__ w2, const float* __restrict__ b2,
    float* __restrict__ out)
{
    extern __shared__ char smem[];
    uint32_t* h_s  = (uint32_t*)(smem + PROJ_HS);
    uint32_t* w_s  = (uint32_t*)(smem + PROJ_WS);
    float*    w2_s = (float*)(smem + PROJ_W2);
    float*    b1_s = (float*)(smem + PROJ_B1);

    int t = threadIdx.x;
    int item0 = blockIdx.x * 128;

    // fused final update (no write-back needed)
    for (int idx = t; idx < 8192; idx += 256) {
        int row = idx >> 6, k = idx & 63;
        size_t gi = (size_t)(item0 + row) * 64 + k;
        float ic = d_invc[(item0 + row) & (NPTS - 1)];
        h_s[row * G_STRIDE + k] = f2tf32(d_h[gi] + d_agg[gi] * ic);
    }
    w2_s[t] = w2[t];
    b1_s[t] = b1[t];
    __syncthreads();

    int w = t >> 5, lane = t & 31;
    int r = lane >> 2, c4 = lane & 3;
    int m0 = w * 16;

    uint32_t a[8][4];
#pragma unroll
    for (int kk = 0; kk < 8; kk++) {
        a[kk][0] = h_s[(m0 + r)     * G_STRIDE + kk * 8 + c4];
        a[kk][1] = h_s[(m0 + r + 8) * G_STRIDE + kk * 8 + c4];
        a[kk][2] = h_s[(m0 + r)     * G_STRIDE + kk * 8 + c4 + 4];
        a[kk][3] = h_s[(m0 + r + 8) * G_STRIDE + kk * 8 + c4 + 4];
    }

    float sum0 = 0.f, sum1 = 0.f;
    for (int ch = 0; ch < 4; ch++) {
        __syncthreads();
        for (int idx = t; idx < 4096; idx += 256) {
            int k = idx >> 6, n = idx & 63;
            w_s[k * W_STRIDE + n] = f2tf32(w1[k * 256 + ch * 64 + n]);
        }
        __syncthreads();

        float acc[8][4];
#pragma unroll
        for (int j = 0; j < 8; j++)
            acc[j][0] = acc[j][1] = acc[j][2] = acc[j][3] = 0.f;
#pragma unroll
        for (int kk = 0; kk < 8; kk++) {
#pragma unroll
            for (int j = 0; j < 8; j++) {
                uint32_t bb[2];
                bb[0] = w_s[(kk * 8 + c4)     * W_STRIDE + j * 8 + r];
                bb[1] = w_s[(kk * 8 + c4 + 4) * W_STRIDE + j * 8 + r];
                mma_tf32(acc[j], a[kk], bb);
            }
        }
#pragma unroll
        for (int j = 0; j < 8; j++) {
            int col = ch * 64 + j * 8 + c4 * 2;
            sum0 += gelu_f(acc[j][0] + b1_s[col]) * w2_s[col]
                  + gelu_f(acc[j][1] + b1_s[col + 1]) * w2_s[col + 1];
            sum1 += gelu_f(acc[j][2] + b1_s[col]) * w2_s[col]
                  + gelu_f(acc[j][3] + b1_s[col + 1]) * w2_s[col + 1];
        }
    }

    sum0 += __shfl_xor_sync(0xffffffffu, sum0, 1);
    sum0 += __shfl_xor_sync(0xffffffffu, sum0, 2);
    sum1 += __shfl_xor_sync(0xffffffffu, sum1, 1);
    sum1 += __shfl_xor_sync(0xffffffffu, sum1, 2);
    if (c4 == 0) {
        float bb = b2[0];
        out[item0 + m0 + r]     = sum0 + bb;
        out[item0 + m0 + r + 8] = sum1 + bb;
    }
}

// ---------------- launch ----------------
extern "C" void kernel_launch(void* const* d_in, const int* in_sizes, int n_in,
                              void* d_out, int out_size) {
    (void)in_sizes; (void)n_in; (void)out_size;
    const float* x    = (const float*)d_in[0];
    const float* pos  = (const float*)d_in[1];
    const void*  ei   = d_in[2];
    const float* lw1  = (const float*)d_in[3];
    const float* lb1  = (const float*)d_in[4];
    const float* lw2  = (const float*)d_in[5];
    const float* lb2  = (const float*)d_in[6];
    const float* kW1  = (const float*)d_in[7];
    const float* kb1  = (const float*)d_in[8];
    const float* kW2  = (const float*)d_in[9];
    const float* kb2  = (const float*)d_in[10];
    const float* pw1  = (const float*)d_in[11];
    const float* pb1  = (const float*)d_in[12];
    const float* pw2  = (const float*)d_in[13];
    const float* pb2  = (const float*)d_in[14];
    float* out = (float*)d_out;

    cudaFuncSetAttribute(k_lift, cudaFuncAttributeMaxDynamicSharedMemorySize, LIFT_SMEM);
    cudaFuncSetAttribute(k_APd,  cudaFuncAttributeMaxDynamicSharedMemorySize, APD_SMEM);
    cudaFuncSetAttribute(k_edge, cudaFuncAttributeMaxDynamicSharedMemorySize, EDGE_SMEM);
    cudaFuncSetAttribute(k_proj, cudaFuncAttributeMaxDynamicSharedMemorySize, PROJ_SMEM);

    k_detect<<<1, 256>>>(ei);
    k_count<<<NEDGE / 256, 256>>>(ei);
    k_scan<<<1, 1024>>>();
    k_sortz<<<NEDGE / 256, 256>>>(ei);
    k_lift<<<(NBATCH * NPTS) / 128, 256, LIFT_SMEM>>>(x, pos, lw1, lb1, lw2, lb2);

    for (int l = 0; l < NLAYER; l++) {
        const float* W1l = kW1 + (size_t)l * 68 * 64;
        const float* b1l = kb1 + (size_t)l * 64;
        const float* W2l = kW2 + (size_t)l * 64 * 64;
        const float* b2l = kb2 + (size_t)l * 64;
        k_APd<<<(NBATCH * NPTS) / 128, 256, APD_SMEM>>>(pos, W1l, b1l, l > 0);
        k_edge<<<NEDGE / 128, 256, EDGE_SMEM>>>(W2l, b2l);
    }

    k_proj<<<(NBATCH * NPTS) / 128, 256, PROJ_SMEM>>>(pw1, pb1, pw2, pb2, out);
}

// round 6
// speedup vs baseline: 3.1591x; 1.0076x over previous
#include <cuda_runtime.h>
#include <cuda_fp16.h>
#include <math.h>
#include <stdint.h>

#define NPTS   32768
#define NEDGE  524288
#define NBATCH 2
#define HID    64
#define LIFTD  256
#define NLAYER 4

// ---------------- scratch ----------------
__device__ float    d_h[NBATCH * NPTS * HID];
__device__ uint32_t d_Ah[NBATCH * NPTS * 32];   // half2-packed A
__device__ uint32_t d_Pdh[NPTS * 32];           // half2-packed Pd
__device__ float    d_agg[NBATCH * NPTS * HID];
__device__ float    d_invc[NPTS];
__device__ int      d_deg[NPTS];
__device__ int      d_cursor[NPTS];
__device__ int      d_ssrc[NEDGE];
__device__ int      d_sdst[NEDGE];
__device__ int      d_is64;

__device__ __forceinline__ float gelu_f(float v) {
    return 0.5f * v * (1.0f + erff(v * 0.70710678118654752f));
}
__device__ __forceinline__ uint32_t f2tf32(float f) {
    uint32_t r;
    asm("cvt.rna.tf32.f32 %0, %1;" : "=r"(r) : "f"(f));
    return r;
}
__device__ __forceinline__ void mma_tf32(float* d, const uint32_t* a, const uint32_t* b) {
    asm volatile("mma.sync.aligned.m16n8k8.row.col.f32.tf32.tf32.f32 "
                 "{%0,%1,%2,%3}, {%4,%5,%6,%7}, {%8,%9}, {%0,%1,%2,%3};"
                 : "+f"(d[0]), "+f"(d[1]), "+f"(d[2]), "+f"(d[3])
                 : "r"(a[0]), "r"(a[1]), "r"(a[2]), "r"(a[3]), "r"(b[0]), "r"(b[1]));
}
__device__ __forceinline__ void mma_fp16(float* d, const uint32_t* a, const uint32_t* b) {
    asm volatile("mma.sync.aligned.m16n8k16.row.col.f32.f16.f16.f32 "
                 "{%0,%1,%2,%3}, {%4,%5,%6,%7}, {%8,%9}, {%0,%1,%2,%3};"
                 : "+f"(d[0]), "+f"(d[1]), "+f"(d[2]), "+f"(d[3])
                 : "r"(a[0]), "r"(a[1]), "r"(a[2]), "r"(a[3]), "r"(b[0]), "r"(b[1]));
}
__device__ __forceinline__ void red4(float* p, float4 v) {
    asm volatile("red.global.add.v4.f32 [%0], {%1,%2,%3,%4};" ::
                 "l"(p), "f"(v.x), "f"(v.y), "f"(v.z), "f"(v.w) : "memory");
}
__device__ __forceinline__ uint32_t pack_h2(float a, float b) {
    __half2 h = __floats2half2_rn(a, b);
    return *(uint32_t*)&h;
}
__device__ __forceinline__ float2 unpack_h2(uint32_t u) {
    return __half22float2(*(__half2*)&u);
}

#define G_STRIDE 68
#define W_STRIDE 72

// ---------------- k_detect: zero deg + dtype detect ----------------
__global__ void __launch_bounds__(256) k_detect(const void* __restrict__ ei) {
    int t = threadIdx.x;
#pragma unroll
    for (int r = 0; r < 32; r++)
        ((int4*)d_deg)[t + 256 * r] = make_int4(0, 0, 0, 0);
    __shared__ int bad;
    if (t == 0) bad = 0;
    __syncthreads();
    if (t < 128) {
        long long v = ((const long long*)ei)[t];
        if (v < 0 || v >= NPTS) atomicOr(&bad, 1);
    }
    __syncthreads();
    if (t == 0) d_is64 = bad ? 0 : 1;
}

// ---------------- k_count ----------------
__global__ void k_count(const void* __restrict__ ei) {
    int e = blockIdx.x * blockDim.x + threadIdx.x;
    if (e < NEDGE) {
        int dd = d_is64 ? (int)((const long long*)ei)[NEDGE + e]
                        : ((const int*)ei)[NEDGE + e];
        atomicAdd(&d_deg[dd], 1);
    }
}

// ---------------- k_scan ----------------
__global__ void __launch_bounds__(1024) k_scan() {
    __shared__ int wsum[32];
    int t = threadIdx.x, lane = t & 31, warp = t >> 5;
    int base = t * 32;
    int v[32];
    int s = 0;
#pragma unroll
    for (int i = 0; i < 32; i++) { v[i] = d_deg[base + i]; s += v[i]; }
    int sc = s;
#pragma unroll
    for (int o = 1; o < 32; o <<= 1) {
        int n = __shfl_up_sync(0xffffffffu, sc, o);
        if (lane >= o) sc += n;
    }
    if (lane == 31) wsum[warp] = sc;
    __syncthreads();
    if (warp == 0) {
        int ws = wsum[lane];
#pragma unroll
        for (int o = 1; o < 32; o <<= 1) {
            int n = __shfl_up_sync(0xffffffffu, ws, o);
            if (lane >= o) ws += n;
        }
        wsum[lane] = ws;
    }
    __syncthreads();
    int off = (warp > 0 ? wsum[warp - 1] : 0) + (sc - s);
#pragma unroll
    for (int i = 0; i < 32; i++) {
        d_cursor[base + i] = off;
        d_invc[base + i] = 1.0f / fmaxf((float)v[i], 1.0f);
        off += v[i];
    }
}

// ---------------- k_sortz: scatter sorted edges + zero agg ----------------
__global__ void __launch_bounds__(256) k_sortz(const void* __restrict__ ei) {
    int e = blockIdx.x * 256 + threadIdx.x;
    int is64 = d_is64;
    int ss, dd;
    if (is64) {
        ss = (int)((const long long*)ei)[e];
        dd = (int)((const long long*)ei)[NEDGE + e];
    } else {
        ss = ((const int*)ei)[e];
        dd = ((const int*)ei)[NEDGE + e];
    }
    int p = atomicAdd(&d_cursor[dd], 1);
    d_ssrc[p] = ss;
    d_sdst[p] = dd;
    ((float4*)d_agg)[e] = make_float4(0.f, 0.f, 0.f, 0.f);
    ((float4*)d_agg)[e + NEDGE] = make_float4(0.f, 0.f, 0.f, 0.f);
}

// ---------------- k_lift: mma tf32, 128 items/block ----------------
#define LIFT_IN   0
#define LIFT_B2   3072
#define LIFT_TS   3328
#define LIFT_WS   (3328 + 34816)
#define LIFT_SMEM (LIFT_WS + 18432)

__global__ void __launch_bounds__(256) k_lift(
    const float* __restrict__ x, const float* __restrict__ pos,
    const float* __restrict__ w1, const float* __restrict__ b1,
    const float* __restrict__ w2, const float* __restrict__ b2)
{
    extern __shared__ char smem[];
    float*    in_s = (float*)(smem + LIFT_IN);
    float*    b2_s = (float*)(smem + LIFT_B2);
    uint32_t* t_s  = (uint32_t*)(smem + LIFT_TS);
    float*    t_sf = (float*)(smem + LIFT_TS);
    uint32_t* w_s  = (uint32_t*)(smem + LIFT_WS);

    int t = threadIdx.x;
    int item0 = blockIdx.x * 128;

    for (int idx = t; idx < 640; idx += 256) {
        int j = idx / 5, i = idx % 5;
        int item = item0 + j;
        int b = item >> 15, n = item & (NPTS - 1);
        in_s[j * 6 + i] = (i < 3) ? x[((size_t)b * NPTS + n) * 3 + i] : pos[n * 2 + (i - 3)];
    }
    if (t < 64) b2_s[t] = b2[t];
    __syncthreads();

    int c  = t & 63, jg = t >> 6;
    int w  = t >> 5, lane = t & 31;
    int r  = lane >> 2, c4 = lane & 3;
    int m0 = w * 16;

    float acc[8][4];
#pragma unroll
    for (int j = 0; j < 8; j++)
        acc[j][0] = acc[j][1] = acc[j][2] = acc[j][3] = 0.f;

    for (int ch = 0; ch < 4; ch++) {
        int cc = ch * 64 + c;
        float w0 = w1[cc], wA = w1[LIFTD + cc], wB = w1[2 * LIFTD + cc];
        float wC = w1[3 * LIFTD + cc], wD = w1[4 * LIFTD + cc];
        float bc = b1[cc];
#pragma unroll 4
        for (int rr = 0; rr < 32; rr++) {
            int row = jg * 32 + rr;
            const float* in = in_s + row * 6;
            float v = bc + in[0] * w0 + in[1] * wA + in[2] * wB + in[3] * wC + in[4] * wD;
            t_s[row * G_STRIDE + c] = f2tf32(gelu_f(v));
        }
        for (int idx = t; idx < 4096; idx += 256) {
            int k = idx >> 6, n = idx & 63;
            w_s[k * W_STRIDE + n] = f2tf32(w2[(ch * 64 + k) * HID + n]);
        }
        __syncthreads();

#pragma unroll
        for (int kk = 0; kk < 8; kk++) {
            uint32_t a[4];
            a[0] = t_s[(m0 + r)     * G_STRIDE + kk * 8 + c4];
            a[1] = t_s[(m0 + r + 8) * G_STRIDE + kk * 8 + c4];
            a[2] = t_s[(m0 + r)     * G_STRIDE + kk * 8 + c4 + 4];
            a[3] = t_s[(m0 + r + 8) * G_STRIDE + kk * 8 + c4 + 4];
#pragma unroll
            for (int j = 0; j < 8; j++) {
                uint32_t bb[2];
                bb[0] = w_s[(kk * 8 + c4)     * W_STRIDE + j * 8 + r];
                bb[1] = w_s[(kk * 8 + c4 + 4) * W_STRIDE + j * 8 + r];
                mma_tf32(acc[j], a, bb);
            }
        }
        __syncthreads();
    }

#pragma unroll
    for (int j = 0; j < 8; j++) {
        int col = j * 8 + c4 * 2;
        float b0 = b2_s[col], b1v = b2_s[col + 1];
        *(float2*)(t_sf + (m0 + r)     * G_STRIDE + col) = make_float2(acc[j][0] + b0, acc[j][1] + b1v);
        *(float2*)(t_sf + (m0 + r + 8) * G_STRIDE + col) = make_float2(acc[j][2] + b0, acc[j][3] + b1v);
    }
    __syncthreads();
    for (int idx = t; idx < 8192; idx += 256) {
        int row = idx >> 6, cc = idx & 63;
        d_h[(size_t)(item0 + row) * 64 + cc] = t_sf[row * G_STRIDE + cc];
    }
}

// ---------------- k_APd: fused update + mma tf32 + Pd, half2 outputs ------
#define APD_POS  0
#define APD_PW   1024
#define APD_HS   2048
#define APD_WS   (2048 + 34816)
#define APD_SMEM (APD_WS + 18432)

__global__ void __launch_bounds__(256) k_APd(
    const float* __restrict__ pos, const float* __restrict__ kW1_l,
    const float* __restrict__ kb1_l, int do_upd)
{
    extern __shared__ char smem[];
    float*    pos_s = (float*)(smem + APD_POS);
    float*    pw_s  = (float*)(smem + APD_PW);
    uint32_t* h_s   = (uint32_t*)(smem + APD_HS);
    uint32_t* w_s   = (uint32_t*)(smem + APD_WS);

    int t = threadIdx.x;
    int item0 = blockIdx.x * 128;

    if (t < 256) {
        int j = t >> 1, i = t & 1;
        int n = (item0 + j) & (NPTS - 1);
        pos_s[j * 2 + i] = pos[n * 2 + i];
    }
    if (t < 256) pw_s[t] = kW1_l[t];

    if (do_upd) {
        for (int idx = t; idx < 8192; idx += 256) {
            int row = idx >> 6, k = idx & 63;
            size_t gi = (size_t)(item0 + row) * 64 + k;
            float ic = d_invc[(item0 + row) & (NPTS - 1)];
            float v = d_h[gi] + d_agg[gi] * ic;
            d_h[gi] = v;
            d_agg[gi] = 0.f;
            h_s[row * G_STRIDE + k] = f2tf32(v);
        }
    } else {
        for (int idx = t; idx < 8192; idx += 256) {
            int row = idx >> 6, k = idx & 63;
            h_s[row * G_STRIDE + k] = f2tf32(d_h[(size_t)(item0 + row) * 64 + k]);
        }
    }
    for (int idx = t; idx < 4096; idx += 256) {
        int k = idx >> 6, n = idx & 63;
        w_s[k * W_STRIDE + n] = f2tf32(kW1_l[(4 + k) * 64 + n]);
    }
    __syncthreads();

    // Pd packed half2 (batch-independent; b0 blocks cover all n once)
    if (item0 < NPTS) {
        for (int idx = t; idx < 4096; idx += 256) {
            int row = idx >> 5, c2 = idx & 31;
            int n = item0 + row, c = c2 * 2;
            float p0 = pos_s[row * 2], p1 = pos_s[row * 2 + 1];
            float v0 = kb1_l[c]     + p0 * pw_s[128 + c]     + p1 * pw_s[192 + c];
            float v1 = kb1_l[c + 1] + p0 * pw_s[128 + c + 1] + p1 * pw_s[192 + c + 1];
            d_Pdh[(size_t)n * 32 + c2] = pack_h2(v0, v1);
        }
    }

    int w = t >> 5, lane = t & 31;
    int r = lane >> 2, c4 = lane & 3;
    int m0 = w * 16;

    float acc[8][4];
#pragma unroll
    for (int j = 0; j < 8; j++)
        acc[j][0] = acc[j][1] = acc[j][2] = acc[j][3] = 0.f;

#pragma unroll
    for (int kk = 0; kk < 8; kk++) {
        uint32_t a[4];
        a[0] = h_s[(m0 + r)     * G_STRIDE + kk * 8 + c4];
        a[1] = h_s[(m0 + r + 8) * G_STRIDE + kk * 8 + c4];
        a[2] = h_s[(m0 + r)     * G_STRIDE + kk * 8 + c4 + 4];
        a[3] = h_s[(m0 + r + 8) * G_STRIDE + kk * 8 + c4 + 4];
#pragma unroll
        for (int j = 0; j < 8; j++) {
            uint32_t bb[2];
            bb[0] = w_s[(kk * 8 + c4)     * W_STRIDE + j * 8 + r];
            bb[1] = w_s[(kk * 8 + c4 + 4) * W_STRIDE + j * 8 + r];
            mma_tf32(acc[j], a, bb);
        }
    }
    __syncthreads();

    // epilogue: add pos terms, pack half2, stage (stride 36, conflict-free)
    float p00 = pos_s[(m0 + r) * 2],     p01 = pos_s[(m0 + r) * 2 + 1];
    float p10 = pos_s[(m0 + r + 8) * 2], p11 = pos_s[(m0 + r + 8) * 2 + 1];
#pragma unroll
    for (int j = 0; j < 8; j++) {
        int col = j * 8 + c4 * 2;
        float w00 = pw_s[col], w01 = pw_s[col + 1];
        float w10 = pw_s[64 + col], w11 = pw_s[64 + col + 1];
        h_s[(m0 + r) * 36 + j * 4 + c4] =
            pack_h2(acc[j][0] + p00 * w00 + p01 * w10, acc[j][1] + p00 * w01 + p01 * w11);
        h_s[(m0 + r + 8) * 36 + j * 4 + c4] =
            pack_h2(acc[j][2] + p10 * w00 + p11 * w10, acc[j][3] + p10 * w01 + p11 * w11);
    }
    __syncthreads();
    for (int idx = t; idx < 4096; idx += 256) {
        int row = idx >> 5, cc = idx & 31;
        d_Ah[(size_t)(item0 + row) * 32 + cc] = h_s[row * 36 + cc];
    }
}

// ---------------- k_edge: fp16 mma, both-batch gather, sorted edges -------
#define EG0_OFF  0
#define EG1_OFF  18432
#define EW_OFF   36864
#define EC_OFF   46080
#define EB_OFF   80896
#define ES_OFF   81152
#define ED_OFF   81664
#define EDGE_SMEM 82176
#define GH_STRIDE 36
#define C_STRIDE  68

__global__ void __launch_bounds__(256) k_edge(
    const float* __restrict__ kW2_l, const float* __restrict__ kb2_l)
{
    extern __shared__ char smem[];
    uint32_t* g0_s   = (uint32_t*)(smem + EG0_OFF);
    uint32_t* g1_s   = (uint32_t*)(smem + EG1_OFF);
    uint32_t* w_s    = (uint32_t*)(smem + EW_OFF);
    float*    c_s    = (float*)(smem + EC_OFF);
    float*    bias_s = (float*)(smem + EB_OFF);
    int*      src_s  = (int*)(smem + ES_OFF);
    int*      dst_s  = (int*)(smem + ED_OFF);

    int t = threadIdx.x;
    int e_base = blockIdx.x * 128;

    for (int idx = t; idx < 2048; idx += 256) {
        int i = idx >> 6, n = idx & 63;
        w_s[i * W_STRIDE + n] = pack_h2(kW2_l[(2 * i) * 64 + n], kW2_l[(2 * i + 1) * 64 + n]);
    }
    if (t < 128) {
        src_s[t] = d_ssrc[e_base + t];
        dst_s[t] = d_sdst[e_base + t];
    }
    if (t < 64) bias_s[t] = kb2_l[t];
    __syncthreads();

    int h2i = t & 31, egrp = t >> 5;
    int w  = t >> 5, lane = t & 31;
    int r  = lane >> 2, c4 = lane & 3;
    int m0 = w * 16;
    int ci4 = (t & 15) * 4;
    int e0  = (t >> 4) * 8;

    // phase 1 (both batches): g{b} = fp16(gelu(A{b}[src] + Pd[dst]))
#pragma unroll 4
    for (int i = 0; i < 16; i++) {
        int e = egrp * 16 + i;
        int ss = src_s[e], dd = dst_s[e];
        float2 fpd = unpack_h2(d_Pdh[(size_t)dd * 32 + h2i]);
        float2 f0  = unpack_h2(d_Ah[(size_t)ss * 32 + h2i]);
        float2 f1  = unpack_h2(d_Ah[(size_t)(NPTS + ss) * 32 + h2i]);
        g0_s[e * GH_STRIDE + h2i] = pack_h2(gelu_f(f0.x + fpd.x), gelu_f(f0.y + fpd.y));
        g1_s[e * GH_STRIDE + h2i] = pack_h2(gelu_f(f1.x + fpd.x), gelu_f(f1.y + fpd.y));
    }
    __syncthreads();

    for (int b = 0; b < NBATCH; b++) {
        const uint32_t* gb = b ? g1_s : g0_s;

        float acc[8][4];
#pragma unroll
        for (int j = 0; j < 8; j++) {
            float b0 = bias_s[j * 8 + c4 * 2];
            float b1 = bias_s[j * 8 + c4 * 2 + 1];
            acc[j][0] = b0; acc[j][1] = b1; acc[j][2] = b0; acc[j][3] = b1;
        }
#pragma unroll
        for (int kk = 0; kk < 4; kk++) {
            uint32_t a[4];
            a[0] = gb[(m0 + r)     * GH_STRIDE + kk * 8 + c4];
            a[1] = gb[(m0 + r + 8) * GH_STRIDE + kk * 8 + c4];
            a[2] = gb[(m0 + r)     * GH_STRIDE + kk * 8 + c4 + 4];
            a[3] = gb[(m0 + r + 8) * GH_STRIDE + kk * 8 + c4 + 4];
#pragma unroll
            for (int j = 0; j < 8; j++) {
                uint32_t bb[2];
                bb[0] = w_s[(kk * 8 + c4)     * W_STRIDE + j * 8 + r];
                bb[1] = w_s[(kk * 8 + c4 + 4) * W_STRIDE + j * 8 + r];
                mma_fp16(acc[j], a, bb);
            }
        }

        // stage C (warp-private rows)
#pragma unroll
        for (int j = 0; j < 8; j++) {
            *(float2*)(c_s + (m0 + r)     * C_STRIDE + j * 8 + c4 * 2) =
                make_float2(acc[j][0], acc[j][1]);
            *(float2*)(c_s + (m0 + r + 8) * C_STRIDE + j * 8 + c4 * 2) =
                make_float2(acc[j][2], acc[j][3]);
        }
        __syncthreads();

        // run-accumulated scatter (sorted dst)
        {
            float* aggb = d_agg + (size_t)b * NPTS * 64;
            int cur = dst_s[e0];
            float4 a4 = *(const float4*)(c_s + e0 * C_STRIDE + ci4);
#pragma unroll
            for (int i = 1; i < 8; i++) {
                int e = e0 + i;
                int dd = dst_s[e];
                float4 v = *(const float4*)(c_s + e * C_STRIDE + ci4);
                if (dd != cur) {
                    red4(aggb + (size_t)cur * 64 + ci4, a4);
                    a4 = v; cur = dd;
                } else {
                    a4.x += v.x; a4.y += v.y; a4.z += v.z; a4.w += v.w;
                }
            }
            red4(aggb + (size_t)cur * 64 + ci4, a4);
        }
        __syncthreads();   // c_s reuse for next batch
    }
}

// ---------------- k_proj: fused final update + mma tf32 ----------------
#define PROJ_HS   0
#define PROJ_WS   34816
#define PROJ_W2   (34816 + 18432)
#define PROJ_B1   (PROJ_W2 + 1024)
#define PROJ_SMEM (PROJ_B1 + 1024)

__global__ void __launch_bounds__(256) k_proj(
    const float* __restrict__ w1, const float* __restrict__ b1,
    const float* __restrict__ w2, const float* __restrict__ b2,
    float* __restrict__ out)
{
    extern __shared__ char smem[];
    uint32_t* h_s  = (uint32_t*)(smem + PROJ_HS);
    uint32_t* w_s  = (uint32_t*)(smem + PROJ_WS);
    float*    w2_s = (float*)(smem + PROJ_W2);
    float*    b1_s = (float*)(smem + PROJ_B1);

    int t = threadIdx.x;
    int item0 = blockIdx.x * 128;

    for (int idx = t; idx < 8192; idx += 256) {
        int row = idx >> 6, k = idx & 63;
        size_t gi = (size_t)(item0 + row) * 64 + k;
        float ic = d_invc[(item0 + row) & (NPTS - 1)];
        h_s[row * G_STRIDE + k] = f2tf32(d_h[gi] + d_agg[gi] * ic);
    }
    w2_s[t] = w2[t];
    b1_s[t] = b1[t];
    __syncthreads();

    int w = t >> 5, lane = t & 31;
    int r = lane >> 2, c4 = lane & 3;
    int m0 = w * 16;

    uint32_t a[8][4];
#pragma unroll
    for (int kk = 0; kk < 8; kk++) {
        a[kk][0] = h_s[(m0 + r)     * G_STRIDE + kk * 8 + c4];
        a[kk][1] = h_s[(m0 + r + 8) * G_STRIDE + kk * 8 + c4];
        a[kk][2] = h_s[(m0 + r)     * G_STRIDE + kk * 8 + c4 + 4];
        a[kk][3] = h_s[(m0 + r + 8) * G_STRIDE + kk * 8 + c4 + 4];
    }

    float sum0 = 0.f, sum1 = 0.f;
    for (int ch = 0; ch < 4; ch++) {
        __syncthreads();
        for (int idx = t; idx < 4096; idx += 256) {
            int k = idx >> 6, n = idx & 63;
            w_s[k * W_STRIDE + n] = f2tf32(w1[k * 256 + ch * 64 + n]);
        }
        __syncthreads();

        float acc[8][4];
#pragma unroll
        for (int j = 0; j < 8; j++)
            acc[j][0] = acc[j][1] = acc[j][2] = acc[j][3] = 0.f;
#pragma unroll
        for (int kk = 0; kk < 8; kk++) {
#pragma unroll
            for (int j = 0; j < 8; j++) {
                uint32_t bb[2];
                bb[0] = w_s[(kk * 8 + c4)     * W_STRIDE + j * 8 + r];
                bb[1] = w_s[(kk * 8 + c4 + 4) * W_STRIDE + j * 8 + r];
                mma_tf32(acc[j], a[kk], bb);
            }
        }
#pragma unroll
        for (int j = 0; j < 8; j++) {
            int col = ch * 64 + j * 8 + c4 * 2;
            sum0 += gelu_f(acc[j][0] + b1_s[col]) * w2_s[col]
                  + gelu_f(acc[j][1] + b1_s[col + 1]) * w2_s[col + 1];
            sum1 += gelu_f(acc[j][2] + b1_s[col]) * w2_s[col]
                  + gelu_f(acc[j][3] + b1_s[col + 1]) * w2_s[col + 1];
        }
    }

    sum0 += __shfl_xor_sync(0xffffffffu, sum0, 1);
    sum0 += __shfl_xor_sync(0xffffffffu, sum0, 2);
    sum1 += __shfl_xor_sync(0xffffffffu, sum1, 1);
    sum1 += __shfl_xor_sync(0xffffffffu, sum1, 2);
    if (c4 == 0) {
        float bb = b2[0];
        out[item0 + m0 + r]     = sum0 + bb;
        out[item0 + m0 + r + 8] = sum1 + bb;
    }
}

// ---------------- launch ----------------
extern "C" void kernel_launch(void* const* d_in, const int* in_sizes, int n_in,
                              void* d_out, int out_size) {
    (void)in_sizes; (void)n_in; (void)out_size;
    const float* x    = (const float*)d_in[0];
    const float* pos  = (const float*)d_in[1];
    const void*  ei   = d_in[2];
    const float* lw1  = (const float*)d_in[3];
    const float* lb1  = (const float*)d_in[4];
    const float* lw2  = (const float*)d_in[5];
    const float* lb2  = (const float*)d_in[6];
    const float* kW1  = (const float*)d_in[7];
    const float* kb1  = (const float*)d_in[8];
    const float* kW2  = (const float*)d_in[9];
    const float* kb2  = (const float*)d_in[10];
    const float* pw1  = (const float*)d_in[11];
    const float* pb1  = (const float*)d_in[12];
    const float* pw2  = (const float*)d_in[13];
    const float* pb2  = (const float*)d_in[14];
    float* out = (float*)d_out;

    cudaFuncSetAttribute(k_lift, cudaFuncAttributeMaxDynamicSharedMemorySize, LIFT_SMEM);
    cudaFuncSetAttribute(k_APd,  cudaFuncAttributeMaxDynamicSharedMemorySize, APD_SMEM);
    cudaFuncSetAttribute(k_edge, cudaFuncAttributeMaxDynamicSharedMemorySize, EDGE_SMEM);
    cudaFuncSetAttribute(k_proj, cudaFuncAttributeMaxDynamicSharedMemorySize, PROJ_SMEM);

    // ordering: index 3 (ncu capture slot) = k_APd layer 0
    k_lift<<<(NBATCH * NPTS) / 128, 256, LIFT_SMEM>>>(x, pos, lw1, lb1, lw2, lb2);  // 0
    k_detect<<<1, 256>>>(ei);                                                       // 1
    k_count<<<NEDGE / 256, 256>>>(ei);                                              // 2
    k_APd<<<(NBATCH * NPTS) / 128, 256, APD_SMEM>>>(pos, kW1, kb1, 0);              // 3  (layer 0)
    k_scan<<<1, 1024>>>();                                                          // 4
    k_sortz<<<NEDGE / 256, 256>>>(ei);                                              // 5
    k_edge<<<NEDGE / 128, 256, EDGE_SMEM>>>(kW2, kb2);                              // 6  (layer 0)

    for (int l = 1; l < NLAYER; l++) {
        const float* W1l = kW1 + (size_t)l * 68 * 64;
        const float* b1l = kb1 + (size_t)l * 64;
        const float* W2l = kW2 + (size_t)l * 64 * 64;
        const float* b2l = kb2 + (size_t)l * 64;
        k_APd<<<(NBATCH * NPTS) / 128, 256, APD_SMEM>>>(pos, W1l, b1l, 1);
        k_edge<<<NEDGE / 128, 256, EDGE_SMEM>>>(W2l, b2l);
    }

    k_proj<<<(NBATCH * NPTS) / 128, 256, PROJ_SMEM>>>(pw1, pb1, pw2, pb2, out);
}

// round 7
// speedup vs baseline: 3.4053x; 1.0779x over previous
#include <cuda_runtime.h>
#include <cuda_fp16.h>
#include <math.h>
#include <stdint.h>

#define NPTS   32768
#define NEDGE  524288
#define NBATCH 2
#define HID    64
#define LIFTD  256
#define NLAYER 4

// ---------------- scratch ----------------
__device__ float    d_h[NBATCH * NPTS * HID];
__device__ uint32_t d_Ah[NBATCH * NPTS * 32];   // half2-packed A
__device__ uint32_t d_Pdh[NPTS * 32];           // half2-packed Pd
__device__ float    d_agg[NBATCH * NPTS * HID];
__device__ float    d_invc[NPTS];
__device__ int      d_deg[NPTS];
__device__ int      d_cursor[NPTS];
__device__ int      d_ssrc[NEDGE];
__device__ int      d_sdst[NEDGE];
__device__ int      d_is64;

__device__ __forceinline__ float gelu_f(float v) {
    return 0.5f * v * (1.0f + erff(v * 0.70710678118654752f));
}
__device__ __forceinline__ uint32_t f2tf32(float f) {
    uint32_t r;
    asm("cvt.rna.tf32.f32 %0, %1;" : "=r"(r) : "f"(f));
    return r;
}
__device__ __forceinline__ void mma_tf32(float* d, const uint32_t* a, const uint32_t* b) {
    asm volatile("mma.sync.aligned.m16n8k8.row.col.f32.tf32.tf32.f32 "
                 "{%0,%1,%2,%3}, {%4,%5,%6,%7}, {%8,%9}, {%0,%1,%2,%3};"
                 : "+f"(d[0]), "+f"(d[1]), "+f"(d[2]), "+f"(d[3])
                 : "r"(a[0]), "r"(a[1]), "r"(a[2]), "r"(a[3]), "r"(b[0]), "r"(b[1]));
}
__device__ __forceinline__ void mma_fp16(float* d, const uint32_t* a, const uint32_t* b) {
    asm volatile("mma.sync.aligned.m16n8k16.row.col.f32.f16.f16.f32 "
                 "{%0,%1,%2,%3}, {%4,%5,%6,%7}, {%8,%9}, {%0,%1,%2,%3};"
                 : "+f"(d[0]), "+f"(d[1]), "+f"(d[2]), "+f"(d[3])
                 : "r"(a[0]), "r"(a[1]), "r"(a[2]), "r"(a[3]), "r"(b[0]), "r"(b[1]));
}
__device__ __forceinline__ void red4(float* p, float4 v) {
    asm volatile("red.global.add.v4.f32 [%0], {%1,%2,%3,%4};" ::
                 "l"(p), "f"(v.x), "f"(v.y), "f"(v.z), "f"(v.w) : "memory");
}
__device__ __forceinline__ uint32_t pack_h2(float a, float b) {
    __half2 h = __floats2half2_rn(a, b);
    return *(uint32_t*)&h;
}
__device__ __forceinline__ float2 unpack_h2(uint32_t u) {
    return __half22float2(*(__half2*)&u);
}

#define G_STRIDE 68
#define W_STRIDE 72

// ---------------- k_detect: zero deg + dtype detect ----------------
__global__ void __launch_bounds__(256) k_detect(const void* __restrict__ ei) {
    int t = threadIdx.x;
#pragma unroll
    for (int r = 0; r < 32; r++)
        ((int4*)d_deg)[t + 256 * r] = make_int4(0, 0, 0, 0);
    __shared__ int bad;
    if (t == 0) bad = 0;
    __syncthreads();
    if (t < 128) {
        long long v = ((const long long*)ei)[t];
        if (v < 0 || v >= NPTS) atomicOr(&bad, 1);
    }
    __syncthreads();
    if (t == 0) d_is64 = bad ? 0 : 1;
}

// ---------------- k_count ----------------
__global__ void k_count(const void* __restrict__ ei) {
    int e = blockIdx.x * blockDim.x + threadIdx.x;
    if (e < NEDGE) {
        int dd = d_is64 ? (int)((const long long*)ei)[NEDGE + e]
                        : ((const int*)ei)[NEDGE + e];
        atomicAdd(&d_deg[dd], 1);
    }
}

// ---------------- k_scan ----------------
__global__ void __launch_bounds__(1024) k_scan() {
    __shared__ int wsum[32];
    int t = threadIdx.x, lane = t & 31, warp = t >> 5;
    int base = t * 32;
    int v[32];
    int s = 0;
#pragma unroll
    for (int i = 0; i < 32; i++) { v[i] = d_deg[base + i]; s += v[i]; }
    int sc = s;
#pragma unroll
    for (int o = 1; o < 32; o <<= 1) {
        int n = __shfl_up_sync(0xffffffffu, sc, o);
        if (lane >= o) sc += n;
    }
    if (lane == 31) wsum[warp] = sc;
    __syncthreads();
    if (warp == 0) {
        int ws = wsum[lane];
#pragma unroll
        for (int o = 1; o < 32; o <<= 1) {
            int n = __shfl_up_sync(0xffffffffu, ws, o);
            if (lane >= o) ws += n;
        }
        wsum[lane] = ws;
    }
    __syncthreads();
    int off = (warp > 0 ? wsum[warp - 1] : 0) + (sc - s);
#pragma unroll
    for (int i = 0; i < 32; i++) {
        d_cursor[base + i] = off;
        d_invc[base + i] = 1.0f / fmaxf((float)v[i], 1.0f);
        off += v[i];
    }
}

// ---------------- k_sortz: scatter sorted edges + zero agg ----------------
__global__ void __launch_bounds__(256) k_sortz(const void* __restrict__ ei) {
    int e = blockIdx.x * 256 + threadIdx.x;
    int is64 = d_is64;
    int ss, dd;
    if (is64) {
        ss = (int)((const long long*)ei)[e];
        dd = (int)((const long long*)ei)[NEDGE + e];
    } else {
        ss = ((const int*)ei)[e];
        dd = ((const int*)ei)[NEDGE + e];
    }
    int p = atomicAdd(&d_cursor[dd], 1);
    d_ssrc[p] = ss;
    d_sdst[p] = dd;
    ((float4*)d_agg)[e] = make_float4(0.f, 0.f, 0.f, 0.f);
    ((float4*)d_agg)[e + NEDGE] = make_float4(0.f, 0.f, 0.f, 0.f);
}

// ---------------- k_lift: mma tf32, 128 items/block ----------------
#define LIFT_IN   0
#define LIFT_B2   3072
#define LIFT_TS   3328
#define LIFT_WS   (3328 + 34816)
#define LIFT_SMEM (LIFT_WS + 18432)

__global__ void __launch_bounds__(256) k_lift(
    const float* __restrict__ x, const float* __restrict__ pos,
    const float* __restrict__ w1, const float* __restrict__ b1,
    const float* __restrict__ w2, const float* __restrict__ b2)
{
    extern __shared__ char smem[];
    float*    in_s = (float*)(smem + LIFT_IN);
    float*    b2_s = (float*)(smem + LIFT_B2);
    uint32_t* t_s  = (uint32_t*)(smem + LIFT_TS);
    float*    t_sf = (float*)(smem + LIFT_TS);
    uint32_t* w_s  = (uint32_t*)(smem + LIFT_WS);

    int t = threadIdx.x;
    int item0 = blockIdx.x * 128;

    for (int idx = t; idx < 640; idx += 256) {
        int j = idx / 5, i = idx % 5;
        int item = item0 + j;
        int b = item >> 15, n = item & (NPTS - 1);
        in_s[j * 6 + i] = (i < 3) ? x[((size_t)b * NPTS + n) * 3 + i] : pos[n * 2 + (i - 3)];
    }
    if (t < 64) b2_s[t] = b2[t];
    __syncthreads();

    int c  = t & 63, jg = t >> 6;
    int w  = t >> 5, lane = t & 31;
    int r  = lane >> 2, c4 = lane & 3;
    int m0 = w * 16;

    float acc[8][4];
#pragma unroll
    for (int j = 0; j < 8; j++)
        acc[j][0] = acc[j][1] = acc[j][2] = acc[j][3] = 0.f;

    for (int ch = 0; ch < 4; ch++) {
        int cc = ch * 64 + c;
        float w0 = w1[cc], wA = w1[LIFTD + cc], wB = w1[2 * LIFTD + cc];
        float wC = w1[3 * LIFTD + cc], wD = w1[4 * LIFTD + cc];
        float bc = b1[cc];
#pragma unroll 4
        for (int rr = 0; rr < 32; rr++) {
            int row = jg * 32 + rr;
            const float* in = in_s + row * 6;
            float v = bc + in[0] * w0 + in[1] * wA + in[2] * wB + in[3] * wC + in[4] * wD;
            t_s[row * G_STRIDE + c] = f2tf32(gelu_f(v));
        }
        for (int idx = t; idx < 4096; idx += 256) {
            int k = idx >> 6, n = idx & 63;
            w_s[k * W_STRIDE + n] = f2tf32(w2[(ch * 64 + k) * HID + n]);
        }
        __syncthreads();

#pragma unroll
        for (int kk = 0; kk < 8; kk++) {
            uint32_t a[4];
            a[0] = t_s[(m0 + r)     * G_STRIDE + kk * 8 + c4];
            a[1] = t_s[(m0 + r + 8) * G_STRIDE + kk * 8 + c4];
            a[2] = t_s[(m0 + r)     * G_STRIDE + kk * 8 + c4 + 4];
            a[3] = t_s[(m0 + r + 8) * G_STRIDE + kk * 8 + c4 + 4];
#pragma unroll
            for (int j = 0; j < 8; j++) {
                uint32_t bb[2];
                bb[0] = w_s[(kk * 8 + c4)     * W_STRIDE + j * 8 + r];
                bb[1] = w_s[(kk * 8 + c4 + 4) * W_STRIDE + j * 8 + r];
                mma_tf32(acc[j], a, bb);
            }
        }
        __syncthreads();
    }

#pragma unroll
    for (int j = 0; j < 8; j++) {
        int col = j * 8 + c4 * 2;
        float b0 = b2_s[col], b1v = b2_s[col + 1];
        *(float2*)(t_sf + (m0 + r)     * G_STRIDE + col) = make_float2(acc[j][0] + b0, acc[j][1] + b1v);
        *(float2*)(t_sf + (m0 + r + 8) * G_STRIDE + col) = make_float2(acc[j][2] + b0, acc[j][3] + b1v);
    }
    __syncthreads();
    for (int idx = t; idx < 8192; idx += 256) {
        int row = idx >> 6, cc = idx & 63;
        d_h[(size_t)(item0 + row) * 64 + cc] = t_sf[row * G_STRIDE + cc];
    }
}

// ---------------- k_APd: fused update + mma tf32 + Pd, half2 outputs ------
#define APD_POS  0
#define APD_PW   1024
#define APD_HS   2048
#define APD_WS   (2048 + 34816)
#define APD_SMEM (APD_WS + 18432)

__global__ void __launch_bounds__(256) k_APd(
    const float* __restrict__ pos, const float* __restrict__ kW1_l,
    const float* __restrict__ kb1_l, int do_upd)
{
    extern __shared__ char smem[];
    float*    pos_s = (float*)(smem + APD_POS);
    float*    pw_s  = (float*)(smem + APD_PW);
    uint32_t* h_s   = (uint32_t*)(smem + APD_HS);
    uint32_t* w_s   = (uint32_t*)(smem + APD_WS);

    int t = threadIdx.x;
    int item0 = blockIdx.x * 128;

    if (t < 256) {
        int j = t >> 1, i = t & 1;
        int n = (item0 + j) & (NPTS - 1);
        pos_s[j * 2 + i] = pos[n * 2 + i];
    }
    if (t < 256) pw_s[t] = kW1_l[t];

    if (do_upd) {
        for (int idx = t; idx < 8192; idx += 256) {
            int row = idx >> 6, k = idx & 63;
            size_t gi = (size_t)(item0 + row) * 64 + k;
            float ic = d_invc[(item0 + row) & (NPTS - 1)];
            float v = d_h[gi] + d_agg[gi] * ic;
            d_h[gi] = v;
            d_agg[gi] = 0.f;
            h_s[row * G_STRIDE + k] = f2tf32(v);
        }
    } else {
        for (int idx = t; idx < 8192; idx += 256) {
            int row = idx >> 6, k = idx & 63;
            h_s[row * G_STRIDE + k] = f2tf32(d_h[(size_t)(item0 + row) * 64 + k]);
        }
    }
    for (int idx = t; idx < 4096; idx += 256) {
        int k = idx >> 6, n = idx & 63;
        w_s[k * W_STRIDE + n] = f2tf32(kW1_l[(4 + k) * 64 + n]);
    }
    __syncthreads();

    if (item0 < NPTS) {
        for (int idx = t; idx < 4096; idx += 256) {
            int row = idx >> 5, c2 = idx & 31;
            int n = item0 + row, c = c2 * 2;
            float p0 = pos_s[row * 2], p1 = pos_s[row * 2 + 1];
            float v0 = kb1_l[c]     + p0 * pw_s[128 + c]     + p1 * pw_s[192 + c];
            float v1 = kb1_l[c + 1] + p0 * pw_s[128 + c + 1] + p1 * pw_s[192 + c + 1];
            d_Pdh[(size_t)n * 32 + c2] = pack_h2(v0, v1);
        }
    }

    int w = t >> 5, lane = t & 31;
    int r = lane >> 2, c4 = lane & 3;
    int m0 = w * 16;

    float acc[8][4];
#pragma unroll
    for (int j = 0; j < 8; j++)
        acc[j][0] = acc[j][1] = acc[j][2] = acc[j][3] = 0.f;

#pragma unroll
    for (int kk = 0; kk < 8; kk++) {
        uint32_t a[4];
        a[0] = h_s[(m0 + r)     * G_STRIDE + kk * 8 + c4];
        a[1] = h_s[(m0 + r + 8) * G_STRIDE + kk * 8 + c4];
        a[2] = h_s[(m0 + r)     * G_STRIDE + kk * 8 + c4 + 4];
        a[3] = h_s[(m0 + r + 8) * G_STRIDE + kk * 8 + c4 + 4];
#pragma unroll
        for (int j = 0; j < 8; j++) {
            uint32_t bb[2];
            bb[0] = w_s[(kk * 8 + c4)     * W_STRIDE + j * 8 + r];
            bb[1] = w_s[(kk * 8 + c4 + 4) * W_STRIDE + j * 8 + r];
            mma_tf32(acc[j], a, bb);
        }
    }
    __syncthreads();

    float p00 = pos_s[(m0 + r) * 2],     p01 = pos_s[(m0 + r) * 2 + 1];
    float p10 = pos_s[(m0 + r + 8) * 2], p11 = pos_s[(m0 + r + 8) * 2 + 1];
#pragma unroll
    for (int j = 0; j < 8; j++) {
        int col = j * 8 + c4 * 2;
        float w00 = pw_s[col], w01 = pw_s[col + 1];
        float w10 = pw_s[64 + col], w11 = pw_s[64 + col + 1];
        h_s[(m0 + r) * 36 + j * 4 + c4] =
            pack_h2(acc[j][0] + p00 * w00 + p01 * w10, acc[j][1] + p00 * w01 + p01 * w11);
        h_s[(m0 + r + 8) * 36 + j * 4 + c4] =
            pack_h2(acc[j][2] + p10 * w00 + p11 * w10, acc[j][3] + p10 * w01 + p11 * w11);
    }
    __syncthreads();
    for (int idx = t; idx < 4096; idx += 256) {
        int row = idx >> 5, cc = idx & 31;
        d_Ah[(size_t)(item0 + row) * 32 + cc] = h_s[row * 36 + cc];
    }
}

// ---------------- k_edge: fp16 mma, g/C smem aliased, 4 blocks/SM ---------
// union region: g (128 x 36 u32 = 18432B) aliased under C (128 x 68 f32 = 34816B)
#define EU_OFF   0
#define EW_OFF   34816
#define EB_OFF   44032
#define ES_OFF   44288
#define ED_OFF   44800
#define EDGE_SMEM 45312
#define GH_STRIDE 36
#define C_STRIDE  68

__global__ void __launch_bounds__(256) k_edge(
    const float* __restrict__ kW2_l, const float* __restrict__ kb2_l)
{
    extern __shared__ char smem[];
    uint32_t* g_s    = (uint32_t*)(smem + EU_OFF);
    float*    c_s    = (float*)(smem + EU_OFF);
    uint32_t* w_s    = (uint32_t*)(smem + EW_OFF);
    float*    bias_s = (float*)(smem + EB_OFF);
    int*      src_s  = (int*)(smem + ES_OFF);
    int*      dst_s  = (int*)(smem + ED_OFF);

    int t = threadIdx.x;
    int e_base = blockIdx.x * 128;

    for (int idx = t; idx < 2048; idx += 256) {
        int i = idx >> 6, n = idx & 63;
        w_s[i * W_STRIDE + n] = pack_h2(kW2_l[(2 * i) * 64 + n], kW2_l[(2 * i + 1) * 64 + n]);
    }
    if (t < 128) {
        src_s[t] = d_ssrc[e_base + t];
        dst_s[t] = d_sdst[e_base + t];
    }
    if (t < 64) bias_s[t] = kb2_l[t];

    int h2i = t & 31, egrp = t >> 5;
    int w  = t >> 5, lane = t & 31;
    int r  = lane >> 2, c4 = lane & 3;
    int m0 = w * 16;
    int ci4 = (t & 15) * 4;
    int e0  = (t >> 4) * 8;
    __syncthreads();

    for (int b = 0; b < NBATCH; b++) {
        const uint32_t* Ab = d_Ah + (size_t)b * NPTS * 32;

        // phase 1: g = fp16(gelu(A[src] + Pd[dst]))
#pragma unroll 4
        for (int i = 0; i < 16; i++) {
            int e = egrp * 16 + i;
            int ss = src_s[e], dd = dst_s[e];
            float2 fpd = unpack_h2(d_Pdh[(size_t)dd * 32 + h2i]);
            float2 fa  = unpack_h2(Ab[(size_t)ss * 32 + h2i]);
            g_s[e * GH_STRIDE + h2i] = pack_h2(gelu_f(fa.x + fpd.x), gelu_f(fa.y + fpd.y));
        }
        __syncthreads();

        // phase 2: fp16 mma, warp tile 16 edges x 64 cols
        float acc[8][4];
#pragma unroll
        for (int j = 0; j < 8; j++) {
            float b0 = bias_s[j * 8 + c4 * 2];
            float b1 = bias_s[j * 8 + c4 * 2 + 1];
            acc[j][0] = b0; acc[j][1] = b1; acc[j][2] = b0; acc[j][3] = b1;
        }
#pragma unroll
        for (int kk = 0; kk < 4; kk++) {
            uint32_t a[4];
            a[0] = g_s[(m0 + r)     * GH_STRIDE + kk * 8 + c4];
            a[1] = g_s[(m0 + r + 8) * GH_STRIDE + kk * 8 + c4];
            a[2] = g_s[(m0 + r)     * GH_STRIDE + kk * 8 + c4 + 4];
            a[3] = g_s[(m0 + r + 8) * GH_STRIDE + kk * 8 + c4 + 4];
#pragma unroll
            for (int j = 0; j < 8; j++) {
                uint32_t bb[2];
                bb[0] = w_s[(kk * 8 + c4)     * W_STRIDE + j * 8 + r];
                bb[1] = w_s[(kk * 8 + c4 + 4) * W_STRIDE + j * 8 + r];
                mma_fp16(acc[j], a, bb);
            }
        }
        __syncthreads();   // all warps done reading g -> safe to overwrite with C

        // stage C over the g region
#pragma unroll
        for (int j = 0; j < 8; j++) {
            *(float2*)(c_s + (m0 + r)     * C_STRIDE + j * 8 + c4 * 2) =
                make_float2(acc[j][0], acc[j][1]);
            *(float2*)(c_s + (m0 + r + 8) * C_STRIDE + j * 8 + c4 * 2) =
                make_float2(acc[j][2], acc[j][3]);
        }
        __syncthreads();

        // run-accumulated scatter (sorted dst)
        {
            float* aggb = d_agg + (size_t)b * NPTS * 64;
            int cur = dst_s[e0];
            float4 a4 = *(const float4*)(c_s + e0 * C_STRIDE + ci4);
#pragma unroll
            for (int i = 1; i < 8; i++) {
                int e = e0 + i;
                int dd = dst_s[e];
                float4 v = *(const float4*)(c_s + e * C_STRIDE + ci4);
                if (dd != cur) {
                    red4(aggb + (size_t)cur * 64 + ci4, a4);
                    a4 = v; cur = dd;
                } else {
                    a4.x += v.x; a4.y += v.y; a4.z += v.z; a4.w += v.w;
                }
            }
            red4(aggb + (size_t)cur * 64 + ci4, a4);
        }
        __syncthreads();   // C region reused as g next batch
    }
}

// ---------------- k_proj: fused final update + mma tf32 ----------------
#define PROJ_HS   0
#define PROJ_WS   34816
#define PROJ_W2   (34816 + 18432)
#define PROJ_B1   (PROJ_W2 + 1024)
#define PROJ_SMEM (PROJ_B1 + 1024)

__global__ void __launch_bounds__(256) k_proj(
    const float* __restrict__ w1, const float* __restrict__ b1,
    const float* __restrict__ w2, const float* __restrict__ b2,
    float* __restrict__ out)
{
    extern __shared__ char smem[];
    uint32_t* h_s  = (uint32_t*)(smem + PROJ_HS);
    uint32_t* w_s  = (uint32_t*)(smem + PROJ_WS);
    float*    w2_s = (float*)(smem + PROJ_W2);
    float*    b1_s = (float*)(smem + PROJ_B1);

    int t = threadIdx.x;
    int item0 = blockIdx.x * 128;

    for (int idx = t; idx < 8192; idx += 256) {
        int row = idx >> 6, k = idx & 63;
        size_t gi = (size_t)(item0 + row) * 64 + k;
        float ic = d_invc[(item0 + row) & (NPTS - 1)];
        h_s[row * G_STRIDE + k] = f2tf32(d_h[gi] + d_agg[gi] * ic);
    }
    w2_s[t] = w2[t];
    b1_s[t] = b1[t];
    __syncthreads();

    int w = t >> 5, lane = t & 31;
    int r = lane >> 2, c4 = lane & 3;
    int m0 = w * 16;

    uint32_t a[8][4];
#pragma unroll
    for (int kk = 0; kk < 8; kk++) {
        a[kk][0] = h_s[(m0 + r)     * G_STRIDE + kk * 8 + c4];
        a[kk][1] = h_s[(m0 + r + 8) * G_STRIDE + kk * 8 + c4];
        a[kk][2] = h_s[(m0 + r)     * G_STRIDE + kk * 8 + c4 + 4];
        a[kk][3] = h_s[(m0 + r + 8) * G_STRIDE + kk * 8 + c4 + 4];
    }

    float sum0 = 0.f, sum1 = 0.f;
    for (int ch = 0; ch < 4; ch++) {
        __syncthreads();
        for (int idx = t; idx < 4096; idx += 256) {
            int k = idx >> 6, n = idx & 63;
            w_s[k * W_STRIDE + n] = f2tf32(w1[k * 256 + ch * 64 + n]);
        }
        __syncthreads();

        float acc[8][4];
#pragma unroll
        for (int j = 0; j < 8; j++)
            acc[j][0] = acc[j][1] = acc[j][2] = acc[j][3] = 0.f;
#pragma unroll
        for (int kk = 0; kk < 8; kk++) {
#pragma unroll
            for (int j = 0; j < 8; j++) {
                uint32_t bb[2];
                bb[0] = w_s[(kk * 8 + c4)     * W_STRIDE + j * 8 + r];
                bb[1] = w_s[(kk * 8 + c4 + 4) * W_STRIDE + j * 8 + r];
                mma_tf32(acc[j], a[kk], bb);
            }
        }
#pragma unroll
        for (int j = 0; j < 8; j++) {
            int col = ch * 64 + j * 8 + c4 * 2;
            sum0 += gelu_f(acc[j][0] + b1_s[col]) * w2_s[col]
                  + gelu_f(acc[j][1] + b1_s[col + 1]) * w2_s[col + 1];
            sum1 += gelu_f(acc[j][2] + b1_s[col]) * w2_s[col]
                  + gelu_f(acc[j][3] + b1_s[col + 1]) * w2_s[col + 1];
        }
    }

    sum0 += __shfl_xor_sync(0xffffffffu, sum0, 1);
    sum0 += __shfl_xor_sync(0xffffffffu, sum0, 2);
    sum1 += __shfl_xor_sync(0xffffffffu, sum1, 1);
    sum1 += __shfl_xor_sync(0xffffffffu, sum1, 2);
    if (c4 == 0) {
        float bb = b2[0];
        out[item0 + m0 + r]     = sum0 + bb;
        out[item0 + m0 + r + 8] = sum1 + bb;
    }
}

// ---------------- launch ----------------
extern "C" void kernel_launch(void* const* d_in, const int* in_sizes, int n_in,
                              void* d_out, int out_size) {
    (void)in_sizes; (void)n_in; (void)out_size;
    const float* x    = (const float*)d_in[0];
    const float* pos  = (const float*)d_in[1];
    const void*  ei   = d_in[2];
    const float* lw1  = (const float*)d_in[3];
    const float* lb1  = (const float*)d_in[4];
    const float* lw2  = (const float*)d_in[5];
    const float* lb2  = (const float*)d_in[6];
    const float* kW1  = (const float*)d_in[7];
    const float* kb1  = (const float*)d_in[8];
    const float* kW2  = (const float*)d_in[9];
    const float* kb2  = (const float*)d_in[10];
    const float* pw1  = (const float*)d_in[11];
    const float* pb1  = (const float*)d_in[12];
    const float* pw2  = (const float*)d_in[13];
    const float* pb2  = (const float*)d_in[14];
    float* out = (float*)d_out;

    cudaFuncSetAttribute(k_lift, cudaFuncAttributeMaxDynamicSharedMemorySize, LIFT_SMEM);
    cudaFuncSetAttribute(k_APd,  cudaFuncAttributeMaxDynamicSharedMemorySize, APD_SMEM);
    cudaFuncSetAttribute(k_edge, cudaFuncAttributeMaxDynamicSharedMemorySize, EDGE_SMEM);
    cudaFuncSetAttribute(k_proj, cudaFuncAttributeMaxDynamicSharedMemorySize, PROJ_SMEM);

    // ordering: index 3 (ncu capture slot) = k_edge layer 0
    k_detect<<<1, 256>>>(ei);                                                       // 0
    k_count<<<NEDGE / 256, 256>>>(ei);                                              // 1
    k_scan<<<1, 1024>>>();                                                          // 2  (needs count)
    // NOTE: sortz must precede edge; APd must precede edge; keep index 3 = edge
    // by hoisting its dependencies into 0..2 is impossible (sortz needs scan), so
    // accept index 3 = k_sortz-dependent chain: reorder to put edge at 5 and APd at 4.
    k_sortz<<<NEDGE / 256, 256>>>(ei);                                              // 3
    k_lift<<<(NBATCH * NPTS) / 128, 256, LIFT_SMEM>>>(x, pos, lw1, lb1, lw2, lb2);  // 4
    k_APd<<<(NBATCH * NPTS) / 128, 256, APD_SMEM>>>(pos, kW1, kb1, 0);              // 5
    k_edge<<<NEDGE / 128, 256, EDGE_SMEM>>>(kW2, kb2);                              // 6

    for (int l = 1; l < NLAYER; l++) {
        const float* W1l = kW1 + (size_t)l * 68 * 64;
        const float* b1l = kb1 + (size_t)l * 64;
        const float* W2l = kW2 + (size_t)l * 64 * 64;
        const float* b2l = kb2 + (size_t)l * 64;
        k_APd<<<(NBATCH * NPTS) / 128, 256, APD_SMEM>>>(pos, W1l, b1l, 1);
        k_edge<<<NEDGE / 128, 256, EDGE_SMEM>>>(W2l, b2l);
    }

    k_proj<<<(NBATCH * NPTS) / 128, 256, PROJ_SMEM>>>(pw1, pb1, pw2, pb2, out);
}

// round 8
// speedup vs baseline: 4.1565x; 1.2206x over previous
#include <cuda_runtime.h>
#include <cuda_fp16.h>
#include <math.h>
#include <stdint.h>

#define NPTS   32768
#define NEDGE  524288
#define NBATCH 2
#define HID    64
#define LIFTD  256
#define NLAYER 4

// ---------------- scratch ----------------
__device__ float    d_h[NBATCH * NPTS * HID];
__device__ uint32_t d_Ah[NBATCH * NPTS * 32];   // half2-packed A
__device__ uint32_t d_Pdh[NPTS * 32];           // half2-packed Pd
__device__ float    d_agg[NBATCH * NPTS * HID];
__device__ float    d_invc[NPTS];
__device__ int      d_deg[NPTS];
__device__ int      d_cursor[NPTS];
__device__ int      d_ssrc[NEDGE];
__device__ int      d_sdst[NEDGE];
__device__ int      d_is64;

__device__ __forceinline__ float gelu_f(float v) {
    return 0.5f * v * (1.0f + erff(v * 0.70710678118654752f));
}
// fast tanh-form gelu: HW tanh.approx (sm_75+), ~6 instructions.
// |error| vs exact ~2e-4 absolute; used only where fp16 quantization follows.
__device__ __forceinline__ float gelu_fast(float x) {
    float x2 = x * x;
    float inner = x * fmaf(0.0356774081f, x2, 0.7978845608f);
    float t;
    asm("tanh.approx.f32 %0, %1;" : "=f"(t) : "f"(inner));
    float hx = 0.5f * x;
    return fmaf(hx, t, hx);
}
__device__ __forceinline__ uint32_t f2tf32(float f) {
    uint32_t r;
    asm("cvt.rna.tf32.f32 %0, %1;" : "=r"(r) : "f"(f));
    return r;
}
__device__ __forceinline__ void mma_tf32(float* d, const uint32_t* a, const uint32_t* b) {
    asm volatile("mma.sync.aligned.m16n8k8.row.col.f32.tf32.tf32.f32 "
                 "{%0,%1,%2,%3}, {%4,%5,%6,%7}, {%8,%9}, {%0,%1,%2,%3};"
                 : "+f"(d[0]), "+f"(d[1]), "+f"(d[2]), "+f"(d[3])
                 : "r"(a[0]), "r"(a[1]), "r"(a[2]), "r"(a[3]), "r"(b[0]), "r"(b[1]));
}
__device__ __forceinline__ void mma_fp16(float* d, const uint32_t* a, const uint32_t* b) {
    asm volatile("mma.sync.aligned.m16n8k16.row.col.f32.f16.f16.f32 "
                 "{%0,%1,%2,%3}, {%4,%5,%6,%7}, {%8,%9}, {%0,%1,%2,%3};"
                 : "+f"(d[0]), "+f"(d[1]), "+f"(d[2]), "+f"(d[3])
                 : "r"(a[0]), "r"(a[1]), "r"(a[2]), "r"(a[3]), "r"(b[0]), "r"(b[1]));
}
__device__ __forceinline__ void red4(float* p, float4 v) {
    asm volatile("red.global.add.v4.f32 [%0], {%1,%2,%3,%4};" ::
                 "l"(p), "f"(v.x), "f"(v.y), "f"(v.z), "f"(v.w) : "memory");
}
__device__ __forceinline__ uint32_t pack_h2(float a, float b) {
    __half2 h = __floats2half2_rn(a, b);
    return *(uint32_t*)&h;
}
__device__ __forceinline__ float2 unpack_h2(uint32_t u) {
    return __half22float2(*(__half2*)&u);
}

#define G_STRIDE 68
#define W_STRIDE 72

// ---------------- k_detect: zero deg + dtype detect ----------------
__global__ void __launch_bounds__(256) k_detect(const void* __restrict__ ei) {
    int t = threadIdx.x;
#pragma unroll
    for (int r = 0; r < 32; r++)
        ((int4*)d_deg)[t + 256 * r] = make_int4(0, 0, 0, 0);
    __shared__ int bad;
    if (t == 0) bad = 0;
    __syncthreads();
    if (t < 128) {
        long long v = ((const long long*)ei)[t];
        if (v < 0 || v >= NPTS) atomicOr(&bad, 1);
    }
    __syncthreads();
    if (t == 0) d_is64 = bad ? 0 : 1;
}

// ---------------- k_count ----------------
__global__ void k_count(const void* __restrict__ ei) {
    int e = blockIdx.x * blockDim.x + threadIdx.x;
    if (e < NEDGE) {
        int dd = d_is64 ? (int)((const long long*)ei)[NEDGE + e]
                        : ((const int*)ei)[NEDGE + e];
        atomicAdd(&d_deg[dd], 1);
    }
}

// ---------------- k_scan ----------------
__global__ void __launch_bounds__(1024) k_scan() {
    __shared__ int wsum[32];
    int t = threadIdx.x, lane = t & 31, warp = t >> 5;
    int base = t * 32;
    int v[32];
    int s = 0;
#pragma unroll
    for (int i = 0; i < 32; i++) { v[i] = d_deg[base + i]; s += v[i]; }
    int sc = s;
#pragma unroll
    for (int o = 1; o < 32; o <<= 1) {
        int n = __shfl_up_sync(0xffffffffu, sc, o);
        if (lane >= o) sc += n;
    }
    if (lane == 31) wsum[warp] = sc;
    __syncthreads();
    if (warp == 0) {
        int ws = wsum[lane];
#pragma unroll
        for (int o = 1; o < 32; o <<= 1) {
            int n = __shfl_up_sync(0xffffffffu, ws, o);
            if (lane >= o) ws += n;
        }
        wsum[lane] = ws;
    }
    __syncthreads();
    int off = (warp > 0 ? wsum[warp - 1] : 0) + (sc - s);
#pragma unroll
    for (int i = 0; i < 32; i++) {
        d_cursor[base + i] = off;
        d_invc[base + i] = 1.0f / fmaxf((float)v[i], 1.0f);
        off += v[i];
    }
}

// ---------------- k_sortz: scatter sorted edges + zero agg ----------------
__global__ void __launch_bounds__(256) k_sortz(const void* __restrict__ ei) {
    int e = blockIdx.x * 256 + threadIdx.x;
    int is64 = d_is64;
    int ss, dd;
    if (is64) {
        ss = (int)((const long long*)ei)[e];
        dd = (int)((const long long*)ei)[NEDGE + e];
    } else {
        ss = ((const int*)ei)[e];
        dd = ((const int*)ei)[NEDGE + e];
    }
    int p = atomicAdd(&d_cursor[dd], 1);
    d_ssrc[p] = ss;
    d_sdst[p] = dd;
    ((float4*)d_agg)[e] = make_float4(0.f, 0.f, 0.f, 0.f);
    ((float4*)d_agg)[e + NEDGE] = make_float4(0.f, 0.f, 0.f, 0.f);
}

// ---------------- k_lift: mma tf32, 128 items/block ----------------
#define LIFT_IN   0
#define LIFT_B2   3072
#define LIFT_TS   3328
#define LIFT_WS   (3328 + 34816)
#define LIFT_SMEM (LIFT_WS + 18432)

__global__ void __launch_bounds__(256) k_lift(
    const float* __restrict__ x, const float* __restrict__ pos,
    const float* __restrict__ w1, const float* __restrict__ b1,
    const float* __restrict__ w2, const float* __restrict__ b2)
{
    extern __shared__ char smem[];
    float*    in_s = (float*)(smem + LIFT_IN);
    float*    b2_s = (float*)(smem + LIFT_B2);
    uint32_t* t_s  = (uint32_t*)(smem + LIFT_TS);
    float*    t_sf = (float*)(smem + LIFT_TS);
    uint32_t* w_s  = (uint32_t*)(smem + LIFT_WS);

    int t = threadIdx.x;
    int item0 = blockIdx.x * 128;

    for (int idx = t; idx < 640; idx += 256) {
        int j = idx / 5, i = idx % 5;
        int item = item0 + j;
        int b = item >> 15, n = item & (NPTS - 1);
        in_s[j * 6 + i] = (i < 3) ? x[((size_t)b * NPTS + n) * 3 + i] : pos[n * 2 + (i - 3)];
    }
    if (t < 64) b2_s[t] = b2[t];
    __syncthreads();

    int c  = t & 63, jg = t >> 6;
    int w  = t >> 5, lane = t & 31;
    int r  = lane >> 2, c4 = lane & 3;
    int m0 = w * 16;

    float acc[8][4];
#pragma unroll
    for (int j = 0; j < 8; j++)
        acc[j][0] = acc[j][1] = acc[j][2] = acc[j][3] = 0.f;

    for (int ch = 0; ch < 4; ch++) {
        int cc = ch * 64 + c;
        float w0 = w1[cc], wA = w1[LIFTD + cc], wB = w1[2 * LIFTD + cc];
        float wC = w1[3 * LIFTD + cc], wD = w1[4 * LIFTD + cc];
        float bc = b1[cc];
#pragma unroll 4
        for (int rr = 0; rr < 32; rr++) {
            int row = jg * 32 + rr;
            const float* in = in_s + row * 6;
            float v = bc + in[0] * w0 + in[1] * wA + in[2] * wB + in[3] * wC + in[4] * wD;
            t_s[row * G_STRIDE + c] = f2tf32(gelu_f(v));
        }
        for (int idx = t; idx < 4096; idx += 256) {
            int k = idx >> 6, n = idx & 63;
            w_s[k * W_STRIDE + n] = f2tf32(w2[(ch * 64 + k) * HID + n]);
        }
        __syncthreads();

#pragma unroll
        for (int kk = 0; kk < 8; kk++) {
            uint32_t a[4];
            a[0] = t_s[(m0 + r)     * G_STRIDE + kk * 8 + c4];
            a[1] = t_s[(m0 + r + 8) * G_STRIDE + kk * 8 + c4];
            a[2] = t_s[(m0 + r)     * G_STRIDE + kk * 8 + c4 + 4];
            a[3] = t_s[(m0 + r + 8) * G_STRIDE + kk * 8 + c4 + 4];
#pragma unroll
            for (int j = 0; j < 8; j++) {
                uint32_t bb[2];
                bb[0] = w_s[(kk * 8 + c4)     * W_STRIDE + j * 8 + r];
                bb[1] = w_s[(kk * 8 + c4 + 4) * W_STRIDE + j * 8 + r];
                mma_tf32(acc[j], a, bb);
            }
        }
        __syncthreads();
    }

#pragma unroll
    for (int j = 0; j < 8; j++) {
        int col = j * 8 + c4 * 2;
        float b0 = b2_s[col], b1v = b2_s[col + 1];
        *(float2*)(t_sf + (m0 + r)     * G_STRIDE + col) = make_float2(acc[j][0] + b0, acc[j][1] + b1v);
        *(float2*)(t_sf + (m0 + r + 8) * G_STRIDE + col) = make_float2(acc[j][2] + b0, acc[j][3] + b1v);
    }
    __syncthreads();
    for (int idx = t; idx < 8192; idx += 256) {
        int row = idx >> 6, cc = idx & 63;
        d_h[(size_t)(item0 + row) * 64 + cc] = t_sf[row * G_STRIDE + cc];
    }
}

// ---------------- k_APd: fused update + mma tf32 + Pd, half2 outputs ------
#define APD_POS  0
#define APD_PW   1024
#define APD_HS   2048
#define APD_WS   (2048 + 34816)
#define APD_SMEM (APD_WS + 18432)

__global__ void __launch_bounds__(256) k_APd(
    const float* __restrict__ pos, const float* __restrict__ kW1_l,
    const float* __restrict__ kb1_l, int do_upd)
{
    extern __shared__ char smem[];
    float*    pos_s = (float*)(smem + APD_POS);
    float*    pw_s  = (float*)(smem + APD_PW);
    uint32_t* h_s   = (uint32_t*)(smem + APD_HS);
    uint32_t* w_s   = (uint32_t*)(smem + APD_WS);

    int t = threadIdx.x;
    int item0 = blockIdx.x * 128;

    if (t < 256) {
        int j = t >> 1, i = t & 1;
        int n = (item0 + j) & (NPTS - 1);
        pos_s[j * 2 + i] = pos[n * 2 + i];
    }
    if (t < 256) pw_s[t] = kW1_l[t];

    if (do_upd) {
        for (int idx = t; idx < 8192; idx += 256) {
            int row = idx >> 6, k = idx & 63;
            size_t gi = (size_t)(item0 + row) * 64 + k;
            float ic = d_invc[(item0 + row) & (NPTS - 1)];
            float v = d_h[gi] + d_agg[gi] * ic;
            d_h[gi] = v;
            d_agg[gi] = 0.f;
            h_s[row * G_STRIDE + k] = f2tf32(v);
        }
    } else {
        for (int idx = t; idx < 8192; idx += 256) {
            int row = idx >> 6, k = idx & 63;
            h_s[row * G_STRIDE + k] = f2tf32(d_h[(size_t)(item0 + row) * 64 + k]);
        }
    }
    for (int idx = t; idx < 4096; idx += 256) {
        int k = idx >> 6, n = idx & 63;
        w_s[k * W_STRIDE + n] = f2tf32(kW1_l[(4 + k) * 64 + n]);
    }
    __syncthreads();

    if (item0 < NPTS) {
        for (int idx = t; idx < 4096; idx += 256) {
            int row = idx >> 5, c2 = idx & 31;
            int n = item0 + row, c = c2 * 2;
            float p0 = pos_s[row * 2], p1 = pos_s[row * 2 + 1];
            float v0 = kb1_l[c]     + p0 * pw_s[128 + c]     + p1 * pw_s[192 + c];
            float v1 = kb1_l[c + 1] + p0 * pw_s[128 + c + 1] + p1 * pw_s[192 + c + 1];
            d_Pdh[(size_t)n * 32 + c2] = pack_h2(v0, v1);
        }
    }

    int w = t >> 5, lane = t & 31;
    int r = lane >> 2, c4 = lane & 3;
    int m0 = w * 16;

    float acc[8][4];
#pragma unroll
    for (int j = 0; j < 8; j++)
        acc[j][0] = acc[j][1] = acc[j][2] = acc[j][3] = 0.f;

#pragma unroll
    for (int kk = 0; kk < 8; kk++) {
        uint32_t a[4];
        a[0] = h_s[(m0 + r)     * G_STRIDE + kk * 8 + c4];
        a[1] = h_s[(m0 + r + 8) * G_STRIDE + kk * 8 + c4];
        a[2] = h_s[(m0 + r)     * G_STRIDE + kk * 8 + c4 + 4];
        a[3] = h_s[(m0 + r + 8) * G_STRIDE + kk * 8 + c4 + 4];
#pragma unroll
        for (int j = 0; j < 8; j++) {
            uint32_t bb[2];
            bb[0] = w_s[(kk * 8 + c4)     * W_STRIDE + j * 8 + r];
            bb[1] = w_s[(kk * 8 + c4 + 4) * W_STRIDE + j * 8 + r];
            mma_tf32(acc[j], a, bb);
        }
    }
    __syncthreads();

    float p00 = pos_s[(m0 + r) * 2],     p01 = pos_s[(m0 + r) * 2 + 1];
    float p10 = pos_s[(m0 + r + 8) * 2], p11 = pos_s[(m0 + r + 8) * 2 + 1];
#pragma unroll
    for (int j = 0; j < 8; j++) {
        int col = j * 8 + c4 * 2;
        float w00 = pw_s[col], w01 = pw_s[col + 1];
        float w10 = pw_s[64 + col], w11 = pw_s[64 + col + 1];
        h_s[(m0 + r) * 36 + j * 4 + c4] =
            pack_h2(acc[j][0] + p00 * w00 + p01 * w10, acc[j][1] + p00 * w01 + p01 * w11);
        h_s[(m0 + r + 8) * 36 + j * 4 + c4] =
            pack_h2(acc[j][2] + p10 * w00 + p11 * w10, acc[j][3] + p10 * w01 + p11 * w11);
    }
    __syncthreads();
    for (int idx = t; idx < 4096; idx += 256) {
        int row = idx >> 5, cc = idx & 31;
        d_Ah[(size_t)(item0 + row) * 32 + cc] = h_s[row * 36 + cc];
    }
}

// ---------------- k_edge: fp16 mma, fast gelu, g/C aliased ----------------
#define EU_OFF   0
#define EW_OFF   34816
#define EB_OFF   44032
#define ES_OFF   44288
#define ED_OFF   44800
#define EDGE_SMEM 45312
#define GH_STRIDE 36
#define C_STRIDE  68

__global__ void __launch_bounds__(256) k_edge(
    const float* __restrict__ kW2_l, const float* __restrict__ kb2_l)
{
    extern __shared__ char smem[];
    uint32_t* g_s    = (uint32_t*)(smem + EU_OFF);
    float*    c_s    = (float*)(smem + EU_OFF);
    uint32_t* w_s    = (uint32_t*)(smem + EW_OFF);
    float*    bias_s = (float*)(smem + EB_OFF);
    int*      src_s  = (int*)(smem + ES_OFF);
    int*      dst_s  = (int*)(smem + ED_OFF);

    int t = threadIdx.x;
    int e_base = blockIdx.x * 128;

    for (int idx = t; idx < 2048; idx += 256) {
        int i = idx >> 6, n = idx & 63;
        w_s[i * W_STRIDE + n] = pack_h2(kW2_l[(2 * i) * 64 + n], kW2_l[(2 * i + 1) * 64 + n]);
    }
    if (t < 128) {
        src_s[t] = d_ssrc[e_base + t];
        dst_s[t] = d_sdst[e_base + t];
    }
    if (t < 64) bias_s[t] = kb2_l[t];

    int h2i = t & 31, egrp = t >> 5;
    int w  = t >> 5, lane = t & 31;
    int r  = lane >> 2, c4 = lane & 3;
    int m0 = w * 16;
    int ci4 = (t & 15) * 4;
    int e0  = (t >> 4) * 8;
    __syncthreads();

    for (int b = 0; b < NBATCH; b++) {
        const uint32_t* Ab = d_Ah + (size_t)b * NPTS * 32;

        // phase 1: g = fp16(gelu_fast(A[src] + Pd[dst]))
#pragma unroll 4
        for (int i = 0; i < 16; i++) {
            int e = egrp * 16 + i;
            int ss = src_s[e], dd = dst_s[e];
            float2 fpd = unpack_h2(d_Pdh[(size_t)dd * 32 + h2i]);
            float2 fa  = unpack_h2(Ab[(size_t)ss * 32 + h2i]);
            g_s[e * GH_STRIDE + h2i] = pack_h2(gelu_fast(fa.x + fpd.x), gelu_fast(fa.y + fpd.y));
        }
        __syncthreads();

        // phase 2: fp16 mma, warp tile 16 edges x 64 cols
        float acc[8][4];
#pragma unroll
        for (int j = 0; j < 8; j++) {
            float b0 = bias_s[j * 8 + c4 * 2];
            float b1 = bias_s[j * 8 + c4 * 2 + 1];
            acc[j][0] = b0; acc[j][1] = b1; acc[j][2] = b0; acc[j][3] = b1;
        }
#pragma unroll
        for (int kk = 0; kk < 4; kk++) {
            uint32_t a[4];
            a[0] = g_s[(m0 + r)     * GH_STRIDE + kk * 8 + c4];
            a[1] = g_s[(m0 + r + 8) * GH_STRIDE + kk * 8 + c4];
            a[2] = g_s[(m0 + r)     * GH_STRIDE + kk * 8 + c4 + 4];
            a[3] = g_s[(m0 + r + 8) * GH_STRIDE + kk * 8 + c4 + 4];
#pragma unroll
            for (int j = 0; j < 8; j++) {
                uint32_t bb[2];
                bb[0] = w_s[(kk * 8 + c4)     * W_STRIDE + j * 8 + r];
                bb[1] = w_s[(kk * 8 + c4 + 4) * W_STRIDE + j * 8 + r];
                mma_fp16(acc[j], a, bb);
            }
        }
        __syncthreads();   // all warps done reading g -> safe to overwrite with C

        // stage C over the g region
#pragma unroll
        for (int j = 0; j < 8; j++) {
            *(float2*)(c_s + (m0 + r)     * C_STRIDE + j * 8 + c4 * 2) =
                make_float2(acc[j][0], acc[j][1]);
            *(float2*)(c_s + (m0 + r + 8) * C_STRIDE + j * 8 + c4 * 2) =
                make_float2(acc[j][2], acc[j][3]);
        }
        __syncthreads();

        // run-accumulated scatter (sorted dst)
        {
            float* aggb = d_agg + (size_t)b * NPTS * 64;
            int cur = dst_s[e0];
            float4 a4 = *(const float4*)(c_s + e0 * C_STRIDE + ci4);
#pragma unroll
            for (int i = 1; i < 8; i++) {
                int e = e0 + i;
                int dd = dst_s[e];
                float4 v = *(const float4*)(c_s + e * C_STRIDE + ci4);
                if (dd != cur) {
                    red4(aggb + (size_t)cur * 64 + ci4, a4);
                    a4 = v; cur = dd;
                } else {
                    a4.x += v.x; a4.y += v.y; a4.z += v.z; a4.w += v.w;
                }
            }
            red4(aggb + (size_t)cur * 64 + ci4, a4);
        }
        __syncthreads();   // C region reused as g next batch
    }
}

// ---------------- k_proj: fused final update + mma tf32 ----------------
#define PROJ_HS   0
#define PROJ_WS   34816
#define PROJ_W2   (34816 + 18432)
#define PROJ_B1   (PROJ_W2 + 1024)
#define PROJ_SMEM (PROJ_B1 + 1024)

__global__ void __launch_bounds__(256) k_proj(
    const float* __restrict__ w1, const float* __restrict__ b1,
    const float* __restrict__ w2, const float* __restrict__ b2,
    float* __restrict__ out)
{
    extern __shared__ char smem[];
    uint32_t* h_s  = (uint32_t*)(smem + PROJ_HS);
    uint32_t* w_s  = (uint32_t*)(smem + PROJ_WS);
    float*    w2_s = (float*)(smem + PROJ_W2);
    float*    b1_s = (float*)(smem + PROJ_B1);

    int t = threadIdx.x;
    int item0 = blockIdx.x * 128;

    for (int idx = t; idx < 8192; idx += 256) {
        int row = idx >> 6, k = idx & 63;
        size_t gi = (size_t)(item0 + row) * 64 + k;
        float ic = d_invc[(item0 + row) & (NPTS - 1)];
        h_s[row * G_STRIDE + k] = f2tf32(d_h[gi] + d_agg[gi] * ic);
    }
    w2_s[t] = w2[t];
    b1_s[t] = b1[t];
    __syncthreads();

    int w = t >> 5, lane = t & 31;
    int r = lane >> 2, c4 = lane & 3;
    int m0 = w * 16;

    uint32_t a[8][4];
#pragma unroll
    for (int kk = 0; kk < 8; kk++) {
        a[kk][0] = h_s[(m0 + r)     * G_STRIDE + kk * 8 + c4];
        a[kk][1] = h_s[(m0 + r + 8) * G_STRIDE + kk * 8 + c4];
        a[kk][2] = h_s[(m0 + r)     * G_STRIDE + kk * 8 + c4 + 4];
        a[kk][3] = h_s[(m0 + r + 8) * G_STRIDE + kk * 8 + c4 + 4];
    }

    float sum0 = 0.f, sum1 = 0.f;
    for (int ch = 0; ch < 4; ch++) {
        __syncthreads();
        for (int idx = t; idx < 4096; idx += 256) {
            int k = idx >> 6, n = idx & 63;
            w_s[k * W_STRIDE + n] = f2tf32(w1[k * 256 + ch * 64 + n]);
        }
        __syncthreads();

        float acc[8][4];
#pragma unroll
        for (int j = 0; j < 8; j++)
            acc[j][0] = acc[j][1] = acc[j][2] = acc[j][3] = 0.f;
#pragma unroll
        for (int kk = 0; kk < 8; kk++) {
#pragma unroll
            for (int j = 0; j < 8; j++) {
                uint32_t bb[2];
                bb[0] = w_s[(kk * 8 + c4)     * W_STRIDE + j * 8 + r];
                bb[1] = w_s[(kk * 8 + c4 + 4) * W_STRIDE + j * 8 + r];
                mma_tf32(acc[j], a[kk], bb);
            }
        }
#pragma unroll
        for (int j = 0; j < 8; j++) {
            int col = ch * 64 + j * 8 + c4 * 2;
            sum0 += gelu_f(acc[j][0] + b1_s[col]) * w2_s[col]
                  + gelu_f(acc[j][1] + b1_s[col + 1]) * w2_s[col + 1];
            sum1 += gelu_f(acc[j][2] + b1_s[col]) * w2_s[col]
                  + gelu_f(acc[j][3] + b1_s[col + 1]) * w2_s[col + 1];
        }
    }

    sum0 += __shfl_xor_sync(0xffffffffu, sum0, 1);
    sum0 += __shfl_xor_sync(0xffffffffu, sum0, 2);
    sum1 += __shfl_xor_sync(0xffffffffu, sum1, 1);
    sum1 += __shfl_xor_sync(0xffffffffu, sum1, 2);
    if (c4 == 0) {
        float bb = b2[0];
        out[item0 + m0 + r]     = sum0 + bb;
        out[item0 + m0 + r + 8] = sum1 + bb;
    }
}

// ---------------- launch ----------------
extern "C" void kernel_launch(void* const* d_in, const int* in_sizes, int n_in,
                              void* d_out, int out_size) {
    (void)in_sizes; (void)n_in; (void)out_size;
    const float* x    = (const float*)d_in[0];
    const float* pos  = (const float*)d_in[1];
    const void*  ei   = d_in[2];
    const float* lw1  = (const float*)d_in[3];
    const float* lb1  = (const float*)d_in[4];
    const float* lw2  = (const float*)d_in[5];
    const float* lb2  = (const float*)d_in[6];
    const float* kW1  = (const float*)d_in[7];
    const float* kb1  = (const float*)d_in[8];
    const float* kW2  = (const float*)d_in[9];
    const float* kb2  = (const float*)d_in[10];
    const float* pw1  = (const float*)d_in[11];
    const float* pb1  = (const float*)d_in[12];
    const float* pw2  = (const float*)d_in[13];
    const float* pb2  = (const float*)d_in[14];
    float* out = (float*)d_out;

    cudaFuncSetAttribute(k_lift, cudaFuncAttributeMaxDynamicSharedMemorySize, LIFT_SMEM);
    cudaFuncSetAttribute(k_APd,  cudaFuncAttributeMaxDynamicSharedMemorySize, APD_SMEM);
    cudaFuncSetAttribute(k_edge, cudaFuncAttributeMaxDynamicSharedMemorySize, EDGE_SMEM);
    cudaFuncSetAttribute(k_proj, cudaFuncAttributeMaxDynamicSharedMemorySize, PROJ_SMEM);

    k_detect<<<1, 256>>>(ei);                                                       // 0
    k_count<<<NEDGE / 256, 256>>>(ei);                                              // 1
    k_scan<<<1, 1024>>>();                                                          // 2
    k_sortz<<<NEDGE / 256, 256>>>(ei);                                              // 3
    k_lift<<<(NBATCH * NPTS) / 128, 256, LIFT_SMEM>>>(x, pos, lw1, lb1, lw2, lb2);  // 4
    k_APd<<<(NBATCH * NPTS) / 128, 256, APD_SMEM>>>(pos, kW1, kb1, 0);              // 5
    k_edge<<<NEDGE / 128, 256, EDGE_SMEM>>>(kW2, kb2);                              // 6

    for (int l = 1; l < NLAYER; l++) {
        const float* W1l = kW1 + (size_t)l * 68 * 64;
        const float* b1l = kb1 + (size_t)l * 64;
        const float* W2l = kW2 + (size_t)l * 64 * 64;
        const float* b2l = kb2 + (size_t)l * 64;
        k_APd<<<(NBATCH * NPTS) / 128, 256, APD_SMEM>>>(pos, W1l, b1l, 1);
        k_edge<<<NEDGE / 128, 256, EDGE_SMEM>>>(W2l, b2l);
    }

    k_proj<<<(NBATCH * NPTS) / 128, 256, PROJ_SMEM>>>(pw1, pb1, pw2, pb2, out);
}